// round 13
// baseline (speedup 1.0000x reference)
#include <cuda_runtime.h>
#include <math.h>
#include <stdint.h>

// Problem constants
#define BB   4
#define CI   256
#define CO   256
#define HH   64
#define WWD  64
#define HWSZ (HH*WWD)
#define KKT  9
#define NCH  72            // K = 2304 in chunks of 32 channels

// ---------------- scratch (device globals; no allocation) ----------------
__device__ float  g_xt[BB*HWSZ*CI];            // x in NHWC   (16.8 MB)
__device__ unsigned short g_Bh16[NCH*32*256];  // bf16 hi of dcn_w, [chunk][k32][n256]
__device__ unsigned short g_Bl16[NCH*32*256];  // bf16 lo
__device__ unsigned short g_oBh16[NCH*32*32];  // bf16 hi of offset_w, [chunk][k32][n32]
__device__ unsigned short g_oBl16[NCH*32*32];  // bf16 lo
__device__ float4 g_pw[BB*KKT*HWSZ];           // premasked bilinear weights
__device__ int4   g_po[BB*KKT*HWSZ];           // clamped corner element offsets

// ---------------- helpers ----------------
__device__ __forceinline__ void cp16u(uint32_t dst, const void* src) {
    asm volatile("cp.async.cg.shared.global [%0], [%1], 16;\n" :: "r"(dst), "l"(src));
}
__device__ __forceinline__ void cp_commit() {
    asm volatile("cp.async.commit_group;\n" ::);
}
__device__ __forceinline__ void cp_wait0() {
    asm volatile("cp.async.wait_group 0;\n" ::: "memory");
}
__device__ __forceinline__ uint32_t smem_u32(const void* p) {
    uint32_t r;
    asm("{ .reg .u64 t; cvta.to.shared.u64 t, %1; cvt.u32.u64 %0, t; }" : "=r"(r) : "l"(p));
    return r;
}
__device__ __forceinline__ uint32_t bf16x2(float lo, float hi) {
    uint32_t r;
    asm("cvt.rn.bf16x2.f32 %0, %1, %2;" : "=r"(r) : "f"(hi), "f"(lo));
    return r;
}
__device__ __forceinline__ void ldm_x4(uint32_t* r, uint32_t addr) {
    asm volatile("ldmatrix.sync.aligned.m8n8.x4.shared.b16 {%0,%1,%2,%3}, [%4];"
        : "=r"(r[0]), "=r"(r[1]), "=r"(r[2]), "=r"(r[3]) : "r"(addr));
}
__device__ __forceinline__ void ldm_x4t(uint32_t* r, uint32_t addr) {
    asm volatile("ldmatrix.sync.aligned.m8n8.x4.trans.shared.b16 {%0,%1,%2,%3}, [%4];"
        : "=r"(r[0]), "=r"(r[1]), "=r"(r[2]), "=r"(r[3]) : "r"(addr));
}
__device__ __forceinline__ void mma_bf16(float* d, const uint32_t* a, const uint32_t* b) {
    asm volatile("mma.sync.aligned.m16n8k16.row.col.f32.bf16.bf16.f32 "
        "{%0,%1,%2,%3}, {%4,%5,%6,%7}, {%8,%9}, {%0,%1,%2,%3};"
        : "+f"(d[0]), "+f"(d[1]), "+f"(d[2]), "+f"(d[3])
        : "r"(a[0]), "r"(a[1]), "r"(a[2]), "r"(a[3]), "r"(b[0]), "r"(b[1]));
}
__device__ __forceinline__ void split4(float4 f, uint2& hh, uint2& ll) {
    uint32_t h01 = bf16x2(f.x, f.y), h23 = bf16x2(f.z, f.w);
    float hf0 = __uint_as_float(h01 << 16), hf1 = __uint_as_float(h01 & 0xffff0000u);
    float hf2 = __uint_as_float(h23 << 16), hf3 = __uint_as_float(h23 & 0xffff0000u);
    uint32_t l01 = bf16x2(f.x - hf0, f.y - hf1), l23 = bf16x2(f.z - hf2, f.w - hf3);
    hh = make_uint2(h01, h23);
    ll = make_uint2(l01, l23);
}

// ---------------- kernel 1: NCHW -> NHWC transpose of x ----------------
__global__ void k_transpose_x(const float* __restrict__ x) {
    __shared__ float tile[32][33];
    int b  = blockIdx.z;
    int c0 = blockIdx.y * 32;
    int p0 = blockIdx.x * 32;
    int tx = threadIdx.x, ty = threadIdx.y;   // 32 x 8
    #pragma unroll
    for (int j = 0; j < 32; j += 8)
        tile[ty + j][tx] = x[((b*CI + c0 + ty + j)*HWSZ) + p0 + tx];
    __syncthreads();
    #pragma unroll
    for (int j = 0; j < 32; j += 8)
        g_xt[(b*HWSZ + p0 + ty + j)*CI + c0 + tx] = tile[tx][ty + j];
}

// ---------------- kernel 2: dcn_w -> bf16 hi/lo chunk images ----------------
__global__ void k_prep_b(const float* __restrict__ dw) {
    int idx = blockIdx.x * 256 + threadIdx.x;
    if (idx >= NCH*8192) return;
    int kc = idx >> 13;
    int r  = idx & 8191;
    int k  = r >> 8;
    int n  = r & 255;
    int tap = kc >> 3;
    int c   = (kc & 7)*32 + k;
    float v = dw[(n*CI + c)*KKT + tap];
    uint32_t hp = bf16x2(v, 0.0f);
    float hf = __uint_as_float(hp << 16);
    uint32_t lp = bf16x2(v - hf, 0.0f);
    g_Bh16[idx] = (unsigned short)(hp & 0xffff);
    g_Bl16[idx] = (unsigned short)(lp & 0xffff);
}

// ---------------- kernel 2b: offset_w -> bf16 hi/lo chunk images ----------------
__global__ void k_prep_ob(const float* __restrict__ ow) {
    int idx = blockIdx.x * 256 + threadIdx.x;
    if (idx >= NCH*1024) return;
    int kc = idx >> 10;
    int r  = idx & 1023;
    int k  = r >> 5;
    int n  = r & 31;
    int tap = kc >> 3;
    int c   = (kc & 7)*32 + k;
    float v = (n < 27) ? ow[(n*CI + c)*KKT + tap] : 0.0f;
    uint32_t hp = bf16x2(v, 0.0f);
    float hf = __uint_as_float(hp << 16);
    uint32_t lp = bf16x2(v - hf, 0.0f);
    g_oBh16[idx] = (unsigned short)(hp & 0xffff);
    g_oBl16[idx] = (unsigned short)(lp & 0xffff);
}

// ---------------- kernel 3: offset conv via bf16x3 mma.sync + param build ------------
// (round-7 version, measured 59.8us) grid 256 = (b,h). 128 threads.
#define OOF_A(s, f)  (((s)*2 + (f)) * 5120)
#define OOF_B(s, f)  (20480 + ((s)*2 + (f)) * 2560)
#define OOF_SO       30720
#define OSM_TOTAL    39168

__global__ __launch_bounds__(128) void k_offset(const float* __restrict__ ob) {
    __shared__ __align__(16) char sm[OSM_TOTAL];
    uint32_t su = smem_u32(sm);
    float (*so)[33] = (float(*)[33])(sm + OOF_SO);

    int tid  = threadIdx.x;
    int lane = tid & 31;
    int wrp  = tid >> 5;
    int b    = blockIdx.x >> 6;
    int h    = blockIdx.x & 63;

    int g  = lane >> 3, lr = lane & 7;
    int a_row  = (g & 1)*8 + lr;
    int a_cb   = (g >> 1) * 16;
    int b_krow = (g & 1)*8 + lr;
    int b_cb   = (g >> 1) * 16;

    int gp = tid >> 1;
    int gk = (tid & 1) * 16;
    int br = tid >> 2;
    int bc = (tid & 3) * 8;

    float acc[4][4];
    #pragma unroll
    for (int j = 0; j < 4; ++j)
        #pragma unroll
        for (int q = 0; q < 4; ++q) acc[j][q] = 0.0f;

    bool valid;
    const float* asrc;
    {
        int y = h - 1, xx = gp - 1;
        valid = (y >= 0) && (xx >= 0) && (xx < WWD);
        asrc = g_xt + (((size_t)(b*HWSZ) + (size_t)(y*WWD + xx)) * CI) + gk;
    }

    {
        const char* srcb = (const char*)g_oBh16 + (size_t)br*64 + bc*2;
        const char* srcl = (const char*)g_oBl16 + (size_t)br*64 + bc*2;
        cp16u(su + OOF_B(0,0) + br*80 + bc*2, srcb);
        cp16u(su + OOF_B(1,0) + br*80 + bc*2, srcl);
        cp_commit();
        #pragma unroll
        for (int q = 0; q < 4; ++q) {
            float4 f = make_float4(0,0,0,0);
            if (valid) f = *(const float4*)(asrc + q*4);
            uint2 hh, ll;
            split4(f, hh, ll);
            *(uint2*)(sm + OOF_A(0,0) + gp*80 + (gk + q*4)*2) = hh;
            *(uint2*)(sm + OOF_A(1,0) + gp*80 + (gk + q*4)*2) = ll;
        }
        cp_wait0();
    }
    __syncthreads();

    #pragma unroll 1
    for (int i = 0; i < NCH; ++i) {
        int buf = i & 1;

        float4 v[4];
        if (i < NCH - 1) {
            int sn = i + 1;
            if ((sn & 7) == 0) {
                int t = sn >> 3;
                int y = h + t/3 - 1, xx = gp + t%3 - 1;
                valid = (y >= 0) && (y < HH) && (xx >= 0) && (xx < WWD);
                asrc = g_xt + (((size_t)(b*HWSZ) + (size_t)(y*WWD + xx)) * CI) + gk;
            }
            const float* p = asrc + (sn & 7)*32;
            #pragma unroll
            for (int q = 0; q < 4; ++q)
                v[q] = valid ? *(const float4*)(p + q*4) : make_float4(0,0,0,0);
            const char* srcb = (const char*)g_oBh16 + ((size_t)sn*1024 + br*32)*2 + bc*2;
            const char* srcl = (const char*)g_oBl16 + ((size_t)sn*1024 + br*32)*2 + bc*2;
            cp16u(su + OOF_B(0, buf^1) + br*80 + bc*2, srcb);
            cp16u(su + OOF_B(1, buf^1) + br*80 + bc*2, srcl);
            cp_commit();
        }

        uint32_t baseAh = su + OOF_A(0, buf) + (wrp*16 + a_row)*80 + a_cb;
        uint32_t baseAl = su + OOF_A(1, buf) + (wrp*16 + a_row)*80 + a_cb;
        uint32_t baseBh = su + OOF_B(0, buf) + b_krow*80 + b_cb;
        uint32_t baseBl = su + OOF_B(1, buf) + b_krow*80 + b_cb;
        #pragma unroll
        for (int ks = 0; ks < 2; ++ks) {
            uint32_t aH[4], aL[4];
            ldm_x4(aH, baseAh + ks*32);
            ldm_x4(aL, baseAl + ks*32);
            uint32_t bH[4][2], bL[4][2], t4[4];
            ldm_x4t(t4, baseBh + ks*1280);
            bH[0][0]=t4[0]; bH[0][1]=t4[1]; bH[1][0]=t4[2]; bH[1][1]=t4[3];
            ldm_x4t(t4, baseBh + ks*1280 + 32);
            bH[2][0]=t4[0]; bH[2][1]=t4[1]; bH[3][0]=t4[2]; bH[3][1]=t4[3];
            ldm_x4t(t4, baseBl + ks*1280);
            bL[0][0]=t4[0]; bL[0][1]=t4[1]; bL[1][0]=t4[2]; bL[1][1]=t4[3];
            ldm_x4t(t4, baseBl + ks*1280 + 32);
            bL[2][0]=t4[0]; bL[2][1]=t4[1]; bL[3][0]=t4[2]; bL[3][1]=t4[3];
            #pragma unroll
            for (int nt = 0; nt < 4; ++nt) {
                mma_bf16(acc[nt], aH, bH[nt]);
                mma_bf16(acc[nt], aH, bL[nt]);
                mma_bf16(acc[nt], aL, bH[nt]);
            }
        }

        if (i < NCH - 1) {
            int nb = buf ^ 1;
            #pragma unroll
            for (int q = 0; q < 4; ++q) {
                uint2 hh, ll;
                split4(v[q], hh, ll);
                *(uint2*)(sm + OOF_A(0, nb) + gp*80 + (gk + q*4)*2) = hh;
                *(uint2*)(sm + OOF_A(1, nb) + gp*80 + (gk + q*4)*2) = ll;
            }
            cp_wait0();
        }
        __syncthreads();
    }

    {
        int r0 = wrp*16 + (lane >> 2);
        int c0 = (lane & 3)*2;
        #pragma unroll
        for (int nt = 0; nt < 4; ++nt) {
            int c = c0 + nt*8;
            so[r0][c]       = acc[nt][0];
            so[r0][c+1]     = acc[nt][1];
            so[r0 + 8][c]   = acc[nt][2];
            so[r0 + 8][c+1] = acc[nt][3];
        }
    }
    __syncthreads();

    if (tid < 64) {
        float ov[27];
        #pragma unroll
        for (int oc = 0; oc < 27; ++oc) ov[oc] = so[tid][oc] + ob[oc];

        int w  = tid;
        int hw = h * WWD + w;
        #pragma unroll
        for (int kk = 0; kk < 9; ++kk) {
            float dy = ov[2*kk];
            float dx = ov[2*kk + 1];
            float m  = 1.0f / (1.0f + expf(-ov[18 + kk]));
            int ki = kk / 3, kj = kk % 3;
            float py = (float)(h - 1 + ki) + dy;
            float px = (float)(w - 1 + kj) + dx;
            float fy = floorf(py), fx = floorf(px);
            float wy = py - fy,    wx = px - fx;
            int y0 = (int)fy, x0 = (int)fx;
            int y1 = y0 + 1,  x1 = x0 + 1;

            bool vy0 = (y0 >= 0) && (y0 < HH);
            bool vy1 = (y1 >= 0) && (y1 < HH);
            bool vx0 = (x0 >= 0) && (x0 < WWD);
            bool vx1 = (x1 >= 0) && (x1 < WWD);

            float w00 = (1.0f - wy) * (1.0f - wx) * m * ((vy0 && vx0) ? 1.0f : 0.0f);
            float w01 = (1.0f - wy) * wx          * m * ((vy0 && vx1) ? 1.0f : 0.0f);
            float w10 = wy * (1.0f - wx)          * m * ((vy1 && vx0) ? 1.0f : 0.0f);
            float w11 = wy * wx                   * m * ((vy1 && vx1) ? 1.0f : 0.0f);

            int yc0 = min(max(y0, 0), HH - 1);
            int yc1 = min(max(y1, 0), HH - 1);
            int xc0 = min(max(x0, 0), WWD - 1);
            int xc1 = min(max(x1, 0), WWD - 1);

            int idx = ((b*KKT + kk)*HWSZ) + hw;
            g_pw[idx] = make_float4(w00, w01, w10, w11);
            g_po[idx] = make_int4((yc0*WWD + xc0)*CI, (yc0*WWD + xc1)*CI,
                                  (yc1*WWD + xc0)*CI, (yc1*WWD + xc1)*CI);
        }
    }
}

// ---------------- kernel 4: main GEMM, M-split, 2 CTAs/SM ----------------
// grid 512 = (b, h, m-half), 256 threads (8 warps). M=32 pix, N=256, 32-ch chunks.
// Warp tile: 16 pixels x 64 n -> acc[8][4] = 32 regs.
// SMEM: A planes 32x80B x4 = 10240; B planes 32x528B x4 = 67584; params 9x32x16 x2.
#define MA(s, f)   (((s)*2 + (f)) * 2560)
#define MB(s, f)   (10240 + ((s)*2 + (f)) * 16896)
#define MPW        77824
#define MPO        82432
#define MSM_TOTAL  87040

__global__ __launch_bounds__(256, 2) void k_main(float* __restrict__ out) {
    extern __shared__ char sm[];
    uint32_t su = smem_u32(sm);

    int tid  = threadIdx.x;
    int lane = tid & 31;
    int wid  = tid >> 5;
    int b    = blockIdx.x >> 7;
    int h    = (blockIdx.x >> 1) & 63;
    int mp   = blockIdx.x & 1;           // pixel half of the row
    int hw0  = h * WWD + mp * 32;
    const float* xb = g_xt + (size_t)b * HWSZ * CI;

    // ldmatrix lane mapping
    int g  = lane >> 3, lr = lane & 7;
    int a_row = (g & 1)*8 + lr;
    int a_cb  = (g >> 1) * 16;
    int b_krow = (g & 1)*8 + lr;
    int b_cb  = (g >> 1) * 16;

    int mh = (wid & 1) * 16;          // warp m16 tile
    int ns = (wid >> 1) * 64;         // warp n slice (64 n)

    // A-build: 32 pix x 32 ch / 256 thr -> 4 ch per thread
    int gp = tid >> 3;                // pixel 0..31
    int gk = (tid & 7) * 4;           // channel base
    // B-load: 2 splits x 32 rows x 512B / 256 thr -> 64B per split
    int br  = tid >> 3;               // k row 0..31
    int bsg = (tid & 7) * 64;

    float4* pwp = (float4*)(sm + MPW);
    int4*   pop = (int4*)  (sm + MPO);

    float acc[8][4];
    #pragma unroll
    for (int j = 0; j < 8; ++j)
        #pragma unroll
        for (int q = 0; q < 4; ++q) acc[j][q] = 0.0f;

    // preload params for taps 0 and 1
    if (tid < 64) {
        int t = tid >> 5;
        int pp = tid & 31;
        int pidx = ((b*KKT + t)*HWSZ) + hw0 + pp;
        pwp[t*32 + pp] = g_pw[pidx];
        pop[t*32 + pp] = g_po[pidx];
    }
    __syncthreads();

#define MLOADB(sn, bufw) do { \
    const char* srcb = (const char*)g_Bh16 + ((size_t)(sn)*8192 + br*256)*2 + bsg; \
    const char* srcl = (const char*)g_Bl16 + ((size_t)(sn)*8192 + br*256)*2 + bsg; \
    uint32_t dstb = su + MB(0, bufw) + br*528 + bsg; \
    uint32_t dstl = su + MB(1, bufw) + br*528 + bsg; \
    _Pragma("unroll") \
    for (int q = 0; q < 4; ++q) { \
        cp16u(dstb + q*16, srcb + q*16); \
        cp16u(dstl + q*16, srcl + q*16); \
    } \
    cp_commit(); \
} while (0)

#define MBSTORE(bufw) do { \
    float4 s; \
    s.x = wv.x*v0.x + wv.y*v1.x + wv.z*v2.x + wv.w*v3.x; \
    s.y = wv.x*v0.y + wv.y*v1.y + wv.z*v2.y + wv.w*v3.y; \
    s.z = wv.x*v0.z + wv.y*v1.z + wv.z*v2.z + wv.w*v3.z; \
    s.w = wv.x*v0.w + wv.y*v1.w + wv.z*v2.w + wv.w*v3.w; \
    uint2 hh, ll; \
    split4(s, hh, ll); \
    *(uint2*)(sm + MA(0, bufw) + gp*80 + gk*2) = hh; \
    *(uint2*)(sm + MA(1, bufw) + gp*80 + gk*2) = ll; \
} while (0)

#define MMMA(ks) do { \
    uint32_t Ah = su + MA(0, buf) + (mh + a_row)*80 + a_cb; \
    uint32_t Al = su + MA(1, buf) + (mh + a_row)*80 + a_cb; \
    uint32_t Bh = su + MB(0, buf) + b_krow*528 + ns*2 + b_cb; \
    uint32_t Bl = su + MB(1, buf) + b_krow*528 + ns*2 + b_cb; \
    uint32_t aH[4], aL[4]; \
    ldm_x4(aH, Ah + (ks)*32); \
    ldm_x4(aL, Al + (ks)*32); \
    _Pragma("unroll") \
    for (int nh2 = 0; nh2 < 2; ++nh2) { \
        uint32_t bH[4][2], bL[4][2], t4[4]; \
        ldm_x4t(t4, Bh + (ks)*8448 + nh2*64); \
        bH[0][0]=t4[0]; bH[0][1]=t4[1]; bH[1][0]=t4[2]; bH[1][1]=t4[3]; \
        ldm_x4t(t4, Bh + (ks)*8448 + nh2*64 + 32); \
        bH[2][0]=t4[0]; bH[2][1]=t4[1]; bH[3][0]=t4[2]; bH[3][1]=t4[3]; \
        ldm_x4t(t4, Bl + (ks)*8448 + nh2*64); \
        bL[0][0]=t4[0]; bL[0][1]=t4[1]; bL[1][0]=t4[2]; bL[1][1]=t4[3]; \
        ldm_x4t(t4, Bl + (ks)*8448 + nh2*64 + 32); \
        bL[2][0]=t4[0]; bL[2][1]=t4[1]; bL[3][0]=t4[2]; bL[3][1]=t4[3]; \
        _Pragma("unroll") \
        for (int nt = 0; nt < 4; ++nt) { \
            float* a4 = acc[nh2*4 + nt]; \
            mma_bf16(a4, aH, bH[nt]); \
            mma_bf16(a4, aH, bL[nt]); \
            mma_bf16(a4, aL, bH[nt]); \
        } \
    } \
} while (0)

    // prologue: build chunk 0 into buf 0
    {
        float4 wv = pwp[gp];
        int4   po = pop[gp];
        MLOADB(0, 0);
        const float* base0 = xb + gk;
        float4 v0 = *(const float4*)(base0 + po.x);
        float4 v1 = *(const float4*)(base0 + po.y);
        float4 v2 = *(const float4*)(base0 + po.z);
        float4 v3 = *(const float4*)(base0 + po.w);
        MBSTORE(0);
        cp_wait0();
    }
    __syncthreads();

    #pragma unroll 1
    for (int i = 0; i < NCH; ++i) {
        int buf = i & 1;

        // param ring prefetch
        if ((i & 7) == 0 && i >= 8 && i <= 56 && tid < 32) {
            int t = (i >> 3) + 1;
            int slot = t & 1;
            int pidx = ((b*KKT + t)*HWSZ) + hw0 + tid;
            pwp[slot*32 + tid] = g_pw[pidx];
            pop[slot*32 + tid] = g_po[pidx];
        }

        float4 wv;
        float4 v0, v1, v2, v3;
        if (i < NCH - 1) {
            int sn = i + 1;
            int slot = (sn >> 3) & 1;
            int4 po = pop[slot*32 + gp];
            wv = pwp[slot*32 + gp];
            MLOADB(sn, buf^1);
            const float* base0 = xb + (sn & 7)*32 + gk;
            v0 = *(const float4*)(base0 + po.x);
            v1 = *(const float4*)(base0 + po.y);
            v2 = *(const float4*)(base0 + po.z);
            v3 = *(const float4*)(base0 + po.w);
        }

        MMMA(0);

        if (i < NCH - 1) MBSTORE(buf^1);

        MMMA(1);

        if (i < NCH - 1) cp_wait0();
        __syncthreads();
    }

    // epilogue: out[b][n][h][w]
    {
        float* op = out + ((size_t)(b*CO))*HWSZ + hw0;
        int r = mh + (lane >> 2);
        int c0 = ns + (lane & 3)*2;
        #pragma unroll
        for (int j = 0; j < 8; ++j) {
            int c = c0 + j*8;
            op[(size_t)c*HWSZ + r]           = acc[j][0];
            op[(size_t)(c+1)*HWSZ + r]       = acc[j][1];
            op[(size_t)c*HWSZ + r + 8]       = acc[j][2];
            op[(size_t)(c+1)*HWSZ + r + 8]   = acc[j][3];
        }
    }
}

// ---------------- launch ----------------
extern "C" void kernel_launch(void* const* d_in, const int* in_sizes, int n_in,
                              void* d_out, int out_size) {
    (void)in_sizes; (void)n_in; (void)out_size;
    const float* x  = (const float*)d_in[0];   // (4,256,64,64)
    const float* ow = (const float*)d_in[1];   // (27,256,3,3)
    const float* ob = (const float*)d_in[2];   // (27,)
    const float* dw = (const float*)d_in[3];   // (256,256,3,3)
    float* out = (float*)d_out;                // (4,256,64,64)

    cudaFuncSetAttribute(k_main, cudaFuncAttributeMaxDynamicSharedMemorySize, MSM_TOTAL);

    dim3 tb(32, 8);
    dim3 tg(HWSZ/32, CI/32, BB);
    k_transpose_x<<<tg, tb>>>(x);
    k_prep_b<<<(NCH*8192 + 255)/256, 256>>>(dw);
    k_prep_ob<<<(NCH*1024 + 255)/256, 256>>>(ow);
    k_offset<<<256, 128>>>(ob);
    k_main<<<512, 256, MSM_TOTAL>>>(out);
}

// round 14
// speedup vs baseline: 1.3166x; 1.3166x over previous
#include <cuda_runtime.h>
#include <math.h>
#include <stdint.h>

// Problem constants
#define BB   4
#define CI   256
#define CO   256
#define HH   64
#define WWD  64
#define HWSZ (HH*WWD)
#define KKT  9
#define NCH  72            // K = 2304 in chunks of 32 channels

// ---------------- scratch (device globals; no allocation) ----------------
__device__ float  g_xt[BB*HWSZ*CI];            // x in NHWC   (16.8 MB)
__device__ unsigned short g_Bh16[NCH*32*256];  // bf16 hi of dcn_w, [chunk][k32][n256]
__device__ unsigned short g_Bl16[NCH*32*256];  // bf16 lo
__device__ unsigned short g_oBh16[NCH*32*32];  // bf16 hi of offset_w, [chunk][k32][n32]
__device__ unsigned short g_oBl16[NCH*32*32];  // bf16 lo
__device__ float4 g_pw[BB*KKT*HWSZ];           // premasked bilinear weights
__device__ int4   g_po[BB*KKT*HWSZ];           // clamped corner element offsets

// ---------------- helpers ----------------
__device__ __forceinline__ void cp16u(uint32_t dst, const void* src) {
    asm volatile("cp.async.cg.shared.global [%0], [%1], 16;\n" :: "r"(dst), "l"(src));
}
__device__ __forceinline__ void cp_commit() {
    asm volatile("cp.async.commit_group;\n" ::);
}
__device__ __forceinline__ void cp_wait0() {
    asm volatile("cp.async.wait_group 0;\n" ::: "memory");
}
__device__ __forceinline__ uint32_t smem_u32(const void* p) {
    uint32_t r;
    asm("{ .reg .u64 t; cvta.to.shared.u64 t, %1; cvt.u32.u64 %0, t; }" : "=r"(r) : "l"(p));
    return r;
}
__device__ __forceinline__ uint32_t bf16x2(float lo, float hi) {
    uint32_t r;
    asm("cvt.rn.bf16x2.f32 %0, %1, %2;" : "=r"(r) : "f"(hi), "f"(lo));
    return r;
}
__device__ __forceinline__ void ldm_x4(uint32_t* r, uint32_t addr) {
    asm volatile("ldmatrix.sync.aligned.m8n8.x4.shared.b16 {%0,%1,%2,%3}, [%4];"
        : "=r"(r[0]), "=r"(r[1]), "=r"(r[2]), "=r"(r[3]) : "r"(addr));
}
__device__ __forceinline__ void ldm_x4t(uint32_t* r, uint32_t addr) {
    asm volatile("ldmatrix.sync.aligned.m8n8.x4.trans.shared.b16 {%0,%1,%2,%3}, [%4];"
        : "=r"(r[0]), "=r"(r[1]), "=r"(r[2]), "=r"(r[3]) : "r"(addr));
}
__device__ __forceinline__ void mma_bf16(float* d, const uint32_t* a, const uint32_t* b) {
    asm volatile("mma.sync.aligned.m16n8k16.row.col.f32.bf16.bf16.f32 "
        "{%0,%1,%2,%3}, {%4,%5,%6,%7}, {%8,%9}, {%0,%1,%2,%3};"
        : "+f"(d[0]), "+f"(d[1]), "+f"(d[2]), "+f"(d[3])
        : "r"(a[0]), "r"(a[1]), "r"(a[2]), "r"(a[3]), "r"(b[0]), "r"(b[1]));
}
__device__ __forceinline__ void split4(float4 f, uint2& hh, uint2& ll) {
    uint32_t h01 = bf16x2(f.x, f.y), h23 = bf16x2(f.z, f.w);
    float hf0 = __uint_as_float(h01 << 16), hf1 = __uint_as_float(h01 & 0xffff0000u);
    float hf2 = __uint_as_float(h23 << 16), hf3 = __uint_as_float(h23 & 0xffff0000u);
    uint32_t l01 = bf16x2(f.x - hf0, f.y - hf1), l23 = bf16x2(f.z - hf2, f.w - hf3);
    hh = make_uint2(h01, h23);
    ll = make_uint2(l01, l23);
}

// ---------------- kernel 1: NCHW -> NHWC transpose of x ----------------
__global__ void k_transpose_x(const float* __restrict__ x) {
    __shared__ float tile[32][33];
    int b  = blockIdx.z;
    int c0 = blockIdx.y * 32;
    int p0 = blockIdx.x * 32;
    int tx = threadIdx.x, ty = threadIdx.y;   // 32 x 8
    #pragma unroll
    for (int j = 0; j < 32; j += 8)
        tile[ty + j][tx] = x[((b*CI + c0 + ty + j)*HWSZ) + p0 + tx];
    __syncthreads();
    #pragma unroll
    for (int j = 0; j < 32; j += 8)
        g_xt[(b*HWSZ + p0 + ty + j)*CI + c0 + tx] = tile[tx][ty + j];
}

// ---------------- kernel 2: dcn_w -> bf16 hi/lo chunk images ----------------
__global__ void k_prep_b(const float* __restrict__ dw) {
    int idx = blockIdx.x * 256 + threadIdx.x;
    if (idx >= NCH*8192) return;
    int kc = idx >> 13;
    int r  = idx & 8191;
    int k  = r >> 8;
    int n  = r & 255;
    int tap = kc >> 3;
    int c   = (kc & 7)*32 + k;
    float v = dw[(n*CI + c)*KKT + tap];
    uint32_t hp = bf16x2(v, 0.0f);
    float hf = __uint_as_float(hp << 16);
    uint32_t lp = bf16x2(v - hf, 0.0f);
    g_Bh16[idx] = (unsigned short)(hp & 0xffff);
    g_Bl16[idx] = (unsigned short)(lp & 0xffff);
}

// ---------------- kernel 2b: offset_w -> bf16 hi/lo chunk images ----------------
__global__ void k_prep_ob(const float* __restrict__ ow) {
    int idx = blockIdx.x * 256 + threadIdx.x;
    if (idx >= NCH*1024) return;
    int kc = idx >> 10;
    int r  = idx & 1023;
    int k  = r >> 5;
    int n  = r & 31;
    int tap = kc >> 3;
    int c   = (kc & 7)*32 + k;
    float v = (n < 27) ? ow[(n*CI + c)*KKT + tap] : 0.0f;
    uint32_t hp = bf16x2(v, 0.0f);
    float hf = __uint_as_float(hp << 16);
    uint32_t lp = bf16x2(v - hf, 0.0f);
    g_oBh16[idx] = (unsigned short)(hp & 0xffff);
    g_oBl16[idx] = (unsigned short)(lp & 0xffff);
}

// ---------------- kernel 3: offset conv via bf16x3 mma.sync + param build ------------
// (round-7 version, measured ~59us) grid 256 = (b,h). 128 threads.
#define OOF_A(s, f)  (((s)*2 + (f)) * 5120)
#define OOF_B(s, f)  (20480 + ((s)*2 + (f)) * 2560)
#define OOF_SO       30720
#define OSM_TOTAL    39168

__global__ __launch_bounds__(128) void k_offset(const float* __restrict__ ob) {
    __shared__ __align__(16) char sm[OSM_TOTAL];
    uint32_t su = smem_u32(sm);
    float (*so)[33] = (float(*)[33])(sm + OOF_SO);

    int tid  = threadIdx.x;
    int lane = tid & 31;
    int wrp  = tid >> 5;
    int b    = blockIdx.x >> 6;
    int h    = blockIdx.x & 63;

    int g  = lane >> 3, lr = lane & 7;
    int a_row  = (g & 1)*8 + lr;
    int a_cb   = (g >> 1) * 16;
    int b_krow = (g & 1)*8 + lr;
    int b_cb   = (g >> 1) * 16;

    int gp = tid >> 1;
    int gk = (tid & 1) * 16;
    int br = tid >> 2;
    int bc = (tid & 3) * 8;

    float acc[4][4];
    #pragma unroll
    for (int j = 0; j < 4; ++j)
        #pragma unroll
        for (int q = 0; q < 4; ++q) acc[j][q] = 0.0f;

    bool valid;
    const float* asrc;
    {
        int y = h - 1, xx = gp - 1;
        valid = (y >= 0) && (xx >= 0) && (xx < WWD);
        asrc = g_xt + (((size_t)(b*HWSZ) + (size_t)(y*WWD + xx)) * CI) + gk;
    }

    {
        const char* srcb = (const char*)g_oBh16 + (size_t)br*64 + bc*2;
        const char* srcl = (const char*)g_oBl16 + (size_t)br*64 + bc*2;
        cp16u(su + OOF_B(0,0) + br*80 + bc*2, srcb);
        cp16u(su + OOF_B(1,0) + br*80 + bc*2, srcl);
        cp_commit();
        #pragma unroll
        for (int q = 0; q < 4; ++q) {
            float4 f = make_float4(0,0,0,0);
            if (valid) f = *(const float4*)(asrc + q*4);
            uint2 hh, ll;
            split4(f, hh, ll);
            *(uint2*)(sm + OOF_A(0,0) + gp*80 + (gk + q*4)*2) = hh;
            *(uint2*)(sm + OOF_A(1,0) + gp*80 + (gk + q*4)*2) = ll;
        }
        cp_wait0();
    }
    __syncthreads();

    #pragma unroll 1
    for (int i = 0; i < NCH; ++i) {
        int buf = i & 1;

        float4 v[4];
        if (i < NCH - 1) {
            int sn = i + 1;
            if ((sn & 7) == 0) {
                int t = sn >> 3;
                int y = h + t/3 - 1, xx = gp + t%3 - 1;
                valid = (y >= 0) && (y < HH) && (xx >= 0) && (xx < WWD);
                asrc = g_xt + (((size_t)(b*HWSZ) + (size_t)(y*WWD + xx)) * CI) + gk;
            }
            const float* p = asrc + (sn & 7)*32;
            #pragma unroll
            for (int q = 0; q < 4; ++q)
                v[q] = valid ? *(const float4*)(p + q*4) : make_float4(0,0,0,0);
            const char* srcb = (const char*)g_oBh16 + ((size_t)sn*1024 + br*32)*2 + bc*2;
            const char* srcl = (const char*)g_oBl16 + ((size_t)sn*1024 + br*32)*2 + bc*2;
            cp16u(su + OOF_B(0, buf^1) + br*80 + bc*2, srcb);
            cp16u(su + OOF_B(1, buf^1) + br*80 + bc*2, srcl);
            cp_commit();
        }

        uint32_t baseAh = su + OOF_A(0, buf) + (wrp*16 + a_row)*80 + a_cb;
        uint32_t baseAl = su + OOF_A(1, buf) + (wrp*16 + a_row)*80 + a_cb;
        uint32_t baseBh = su + OOF_B(0, buf) + b_krow*80 + b_cb;
        uint32_t baseBl = su + OOF_B(1, buf) + b_krow*80 + b_cb;
        #pragma unroll
        for (int ks = 0; ks < 2; ++ks) {
            uint32_t aH[4], aL[4];
            ldm_x4(aH, baseAh + ks*32);
            ldm_x4(aL, baseAl + ks*32);
            uint32_t bH[4][2], bL[4][2], t4[4];
            ldm_x4t(t4, baseBh + ks*1280);
            bH[0][0]=t4[0]; bH[0][1]=t4[1]; bH[1][0]=t4[2]; bH[1][1]=t4[3];
            ldm_x4t(t4, baseBh + ks*1280 + 32);
            bH[2][0]=t4[0]; bH[2][1]=t4[1]; bH[3][0]=t4[2]; bH[3][1]=t4[3];
            ldm_x4t(t4, baseBl + ks*1280);
            bL[0][0]=t4[0]; bL[0][1]=t4[1]; bL[1][0]=t4[2]; bL[1][1]=t4[3];
            ldm_x4t(t4, baseBl + ks*1280 + 32);
            bL[2][0]=t4[0]; bL[2][1]=t4[1]; bL[3][0]=t4[2]; bL[3][1]=t4[3];
            #pragma unroll
            for (int nt = 0; nt < 4; ++nt) {
                mma_bf16(acc[nt], aH, bH[nt]);
                mma_bf16(acc[nt], aH, bL[nt]);
                mma_bf16(acc[nt], aL, bH[nt]);
            }
        }

        if (i < NCH - 1) {
            int nb = buf ^ 1;
            #pragma unroll
            for (int q = 0; q < 4; ++q) {
                uint2 hh, ll;
                split4(v[q], hh, ll);
                *(uint2*)(sm + OOF_A(0, nb) + gp*80 + (gk + q*4)*2) = hh;
                *(uint2*)(sm + OOF_A(1, nb) + gp*80 + (gk + q*4)*2) = ll;
            }
            cp_wait0();
        }
        __syncthreads();
    }

    {
        int r0 = wrp*16 + (lane >> 2);
        int c0 = (lane & 3)*2;
        #pragma unroll
        for (int nt = 0; nt < 4; ++nt) {
            int c = c0 + nt*8;
            so[r0][c]       = acc[nt][0];
            so[r0][c+1]     = acc[nt][1];
            so[r0 + 8][c]   = acc[nt][2];
            so[r0 + 8][c+1] = acc[nt][3];
        }
    }
    __syncthreads();

    if (tid < 64) {
        float ov[27];
        #pragma unroll
        for (int oc = 0; oc < 27; ++oc) ov[oc] = so[tid][oc] + ob[oc];

        int w  = tid;
        int hw = h * WWD + w;
        #pragma unroll
        for (int kk = 0; kk < 9; ++kk) {
            float dy = ov[2*kk];
            float dx = ov[2*kk + 1];
            float m  = 1.0f / (1.0f + expf(-ov[18 + kk]));
            int ki = kk / 3, kj = kk % 3;
            float py = (float)(h - 1 + ki) + dy;
            float px = (float)(w - 1 + kj) + dx;
            float fy = floorf(py), fx = floorf(px);
            float wy = py - fy,    wx = px - fx;
            int y0 = (int)fy, x0 = (int)fx;
            int y1 = y0 + 1,  x1 = x0 + 1;

            bool vy0 = (y0 >= 0) && (y0 < HH);
            bool vy1 = (y1 >= 0) && (y1 < HH);
            bool vx0 = (x0 >= 0) && (x0 < WWD);
            bool vx1 = (x1 >= 0) && (x1 < WWD);

            float w00 = (1.0f - wy) * (1.0f - wx) * m * ((vy0 && vx0) ? 1.0f : 0.0f);
            float w01 = (1.0f - wy) * wx          * m * ((vy0 && vx1) ? 1.0f : 0.0f);
            float w10 = wy * (1.0f - wx)          * m * ((vy1 && vx0) ? 1.0f : 0.0f);
            float w11 = wy * wx                   * m * ((vy1 && vx1) ? 1.0f : 0.0f);

            int yc0 = min(max(y0, 0), HH - 1);
            int yc1 = min(max(y1, 0), HH - 1);
            int xc0 = min(max(x0, 0), WWD - 1);
            int xc1 = min(max(x1, 0), WWD - 1);

            int idx = ((b*KKT + kk)*HWSZ) + hw;
            g_pw[idx] = make_float4(w00, w01, w10, w11);
            g_po[idx] = make_int4((yc0*WWD + xc0)*CI, (yc0*WWD + xc1)*CI,
                                  (yc1*WWD + xc0)*CI, (yc1*WWD + xc1)*CI);
        }
    }
}

// ---------------- kernel 4: main GEMM — 8 warps, warp tile 32x64, 2 CTAs/SM ----------
// grid 256 = (b,h), 256 threads. M=64 pix, N=256, 32-ch chunks. No duplicated work.
// SMEM: A planes 64x80B x4 = 20480; B planes 32x528B x4 = 67584; params 4096. = 90KB
#define MA(s, f)   (((s)*2 + (f)) * 5120)
#define MB(s, f)   (20480 + ((s)*2 + (f)) * 16896)
#define MPW        88064
#define MPO        90112
#define MSM_TOTAL  92160

__global__ __launch_bounds__(256, 2) void k_main(float* __restrict__ out) {
    extern __shared__ char sm[];
    uint32_t su = smem_u32(sm);

    int tid  = threadIdx.x;
    int lane = tid & 31;
    int wid  = tid >> 5;
    int b    = blockIdx.x >> 6;
    int h    = blockIdx.x & 63;
    int hw0  = h * WWD;
    const float* xb = g_xt + (size_t)b * HWSZ * CI;

    // ldmatrix lane mapping
    int g  = lane >> 3, lr = lane & 7;
    int a_row = (g & 1)*8 + lr;
    int a_cb  = (g >> 1) * 16;
    int b_krow = (g & 1)*8 + lr;
    int b_cb  = (g >> 1) * 16;

    int mh = (wid & 1) * 32;          // warp m base (2 m16 tiles)
    int ns = (wid >> 1) * 64;         // warp n base (64 n)

    // A-build: 64 pix x 32 ch / 256 thr -> 8 ch/thread in two 4-ch substeps
    int gp = tid >> 2;                // pixel 0..63
    int gk = (tid & 3) * 8;           // channel base
    // B-load: 2 splits x 32 rows x 512B / 256 thr -> 64B per split
    int br  = tid >> 3;               // k row 0..31
    int bsg = (tid & 7) * 64;

    float4* pwp = (float4*)(sm + MPW);
    int4*   pop = (int4*)  (sm + MPO);

    float acc[2][8][4];
    #pragma unroll
    for (int i = 0; i < 2; ++i)
        #pragma unroll
        for (int j = 0; j < 8; ++j)
            #pragma unroll
            for (int q = 0; q < 4; ++q) acc[i][j][q] = 0.0f;

    // preload params for taps 0 and 1
    if (tid < 128) {
        int t = tid >> 6;
        int pp = tid & 63;
        int pidx = ((b*KKT + t)*HWSZ) + hw0 + pp;
        pwp[t*64 + pp] = g_pw[pidx];
        pop[t*64 + pp] = g_po[pidx];
    }
    __syncthreads();

#define MLOADB(sn, bufw) do { \
    const char* srcb = (const char*)g_Bh16 + ((size_t)(sn)*8192 + br*256)*2 + bsg; \
    const char* srcl = (const char*)g_Bl16 + ((size_t)(sn)*8192 + br*256)*2 + bsg; \
    uint32_t dstb = su + MB(0, bufw) + br*528 + bsg; \
    uint32_t dstl = su + MB(1, bufw) + br*528 + bsg; \
    _Pragma("unroll") \
    for (int q = 0; q < 4; ++q) { \
        cp16u(dstb + q*16, srcb + q*16); \
        cp16u(dstl + q*16, srcl + q*16); \
    } \
    cp_commit(); \
} while (0)

// gather+blend+split+store one 4-ch substep (short-lived regs; 2 CTAs hide latency)
#define MGATHSTORE(sn, bufw, sub) do { \
    int slot = ((sn) >> 3) & 1; \
    int4   po = pop[slot*64 + gp]; \
    float4 wv = pwp[slot*64 + gp]; \
    const float* base0 = xb + ((sn) & 7)*32 + gk + (sub)*4; \
    float4 v0 = *(const float4*)(base0 + po.x); \
    float4 v1 = *(const float4*)(base0 + po.y); \
    float4 v2 = *(const float4*)(base0 + po.z); \
    float4 v3 = *(const float4*)(base0 + po.w); \
    float4 s; \
    s.x = wv.x*v0.x + wv.y*v1.x + wv.z*v2.x + wv.w*v3.x; \
    s.y = wv.x*v0.y + wv.y*v1.y + wv.z*v2.y + wv.w*v3.y; \
    s.z = wv.x*v0.z + wv.y*v1.z + wv.z*v2.z + wv.w*v3.z; \
    s.w = wv.x*v0.w + wv.y*v1.w + wv.z*v2.w + wv.w*v3.w; \
    uint2 hh, ll; \
    split4(s, hh, ll); \
    *(uint2*)(sm + MA(0, bufw) + gp*80 + (gk + (sub)*4)*2) = hh; \
    *(uint2*)(sm + MA(1, bufw) + gp*80 + (gk + (sub)*4)*2) = ll; \
} while (0)

#define MMMA(ks) do { \
    uint32_t Ah = su + MA(0, buf) + (mh + a_row)*80 + a_cb; \
    uint32_t Al = su + MA(1, buf) + (mh + a_row)*80 + a_cb; \
    uint32_t Bh = su + MB(0, buf) + b_krow*528 + ns*2 + b_cb; \
    uint32_t Bl = su + MB(1, buf) + b_krow*528 + ns*2 + b_cb; \
    uint32_t aH[2][4], aL[2][4]; \
    ldm_x4(aH[0], Ah + (ks)*32); \
    ldm_x4(aH[1], Ah + 1280 + (ks)*32); \
    ldm_x4(aL[0], Al + (ks)*32); \
    ldm_x4(aL[1], Al + 1280 + (ks)*32); \
    _Pragma("unroll") \
    for (int nh2 = 0; nh2 < 2; ++nh2) { \
        uint32_t bH[4][2], bL[4][2], t4[4]; \
        ldm_x4t(t4, Bh + (ks)*8448 + nh2*64); \
        bH[0][0]=t4[0]; bH[0][1]=t4[1]; bH[1][0]=t4[2]; bH[1][1]=t4[3]; \
        ldm_x4t(t4, Bh + (ks)*8448 + nh2*64 + 32); \
        bH[2][0]=t4[0]; bH[2][1]=t4[1]; bH[3][0]=t4[2]; bH[3][1]=t4[3]; \
        ldm_x4t(t4, Bl + (ks)*8448 + nh2*64); \
        bL[0][0]=t4[0]; bL[0][1]=t4[1]; bL[1][0]=t4[2]; bL[1][1]=t4[3]; \
        ldm_x4t(t4, Bl + (ks)*8448 + nh2*64 + 32); \
        bL[2][0]=t4[0]; bL[2][1]=t4[1]; bL[3][0]=t4[2]; bL[3][1]=t4[3]; \
        _Pragma("unroll") \
        for (int mt = 0; mt < 2; ++mt) \
            _Pragma("unroll") \
            for (int nt = 0; nt < 4; ++nt) { \
                float* a4 = acc[mt][nh2*4 + nt]; \
                mma_bf16(a4, aH[mt], bH[nt]); \
                mma_bf16(a4, aH[mt], bL[nt]); \
                mma_bf16(a4, aL[mt], bH[nt]); \
            } \
    } \
} while (0)

    // prologue: build chunk 0 into buf 0
    {
        MLOADB(0, 0);
        MGATHSTORE(0, 0, 0);
        MGATHSTORE(0, 0, 1);
        cp_wait0();
    }
    __syncthreads();

    #pragma unroll 1
    for (int i = 0; i < NCH; ++i) {
        int buf = i & 1;

        // param ring prefetch
        if ((i & 7) == 0 && i >= 8 && i <= 56 && tid < 64) {
            int t = (i >> 3) + 1;
            int slot = t & 1;
            int pidx = ((b*KKT + t)*HWSZ) + hw0 + tid;
            pwp[slot*64 + tid] = g_pw[pidx];
            pop[slot*64 + tid] = g_po[pidx];
        }

        if (i < NCH - 1) MLOADB(i + 1, buf^1);

        MMMA(0);

        if (i < NCH - 1) MGATHSTORE(i + 1, buf^1, 0);

        MMMA(1);

        if (i < NCH - 1) {
            MGATHSTORE(i + 1, buf^1, 1);
            cp_wait0();
        }
        __syncthreads();
    }

    // epilogue: out[b][n][h][w]
    {
        float* op = out + ((size_t)(b*CO))*HWSZ + hw0;
        int r0 = mh + (lane >> 2);
        int c0 = ns + (lane & 3)*2;
        #pragma unroll
        for (int mt = 0; mt < 2; ++mt) {
            int r = r0 + mt*16;
            #pragma unroll
            for (int j = 0; j < 8; ++j) {
                int c = c0 + j*8;
                op[(size_t)c*HWSZ + r]           = acc[mt][j][0];
                op[(size_t)(c+1)*HWSZ + r]       = acc[mt][j][1];
                op[(size_t)c*HWSZ + r + 8]       = acc[mt][j][2];
                op[(size_t)(c+1)*HWSZ + r + 8]   = acc[mt][j][3];
            }
        }
    }
}

// ---------------- launch ----------------
extern "C" void kernel_launch(void* const* d_in, const int* in_sizes, int n_in,
                              void* d_out, int out_size) {
    (void)in_sizes; (void)n_in; (void)out_size;
    const float* x  = (const float*)d_in[0];   // (4,256,64,64)
    const float* ow = (const float*)d_in[1];   // (27,256,3,3)
    const float* ob = (const float*)d_in[2];   // (27,)
    const float* dw = (const float*)d_in[3];   // (256,256,3,3)
    float* out = (float*)d_out;                // (4,256,64,64)

    cudaFuncSetAttribute(k_main, cudaFuncAttributeMaxDynamicSharedMemorySize, MSM_TOTAL);

    dim3 tb(32, 8);
    dim3 tg(HWSZ/32, CI/32, BB);
    k_transpose_x<<<tg, tb>>>(x);
    k_prep_b<<<(NCH*8192 + 255)/256, 256>>>(dw);
    k_prep_ob<<<(NCH*1024 + 255)/256, 256>>>(ow);
    k_offset<<<256, 128>>>(ob);
    k_main<<<256, 256, MSM_TOTAL>>>(out);
}

// round 15
// speedup vs baseline: 1.8885x; 1.4343x over previous
#include <cuda_runtime.h>
#include <cuda_fp16.h>
#include <math.h>
#include <stdint.h>

// Problem constants
#define BB   4
#define CI   256
#define CO   256
#define HH   64
#define WWD  64
#define HWSZ (HH*WWD)
#define KKT  9
#define NCH  72            // K = 2304 in chunks of 32 channels

// ---------------- scratch (device globals; no allocation) ----------------
__device__ float  g_xt[BB*HWSZ*CI];            // x in NHWC   (16.8 MB)
__device__ unsigned short g_Bh16[NCH*32*256];  // fp16 hi of dcn_w, [chunk][k32][n256]
__device__ unsigned short g_Bl16[NCH*32*256];  // fp16 lo
__device__ unsigned short g_oBh16[NCH*32*32];  // fp16 hi of offset_w, [chunk][k32][n32]
__device__ unsigned short g_oBl16[NCH*32*32];  // fp16 lo

// ---------------- helpers ----------------
__device__ __forceinline__ void cp16u(uint32_t dst, const void* src) {
    asm volatile("cp.async.cg.shared.global [%0], [%1], 16;\n" :: "r"(dst), "l"(src));
}
__device__ __forceinline__ void cp_commit() {
    asm volatile("cp.async.commit_group;\n" ::);
}
__device__ __forceinline__ void cp_wait0() {
    asm volatile("cp.async.wait_group 0;\n" ::: "memory");
}
__device__ __forceinline__ uint32_t smem_u32(const void* p) {
    uint32_t r;
    asm("{ .reg .u64 t; cvta.to.shared.u64 t, %1; cvt.u32.u64 %0, t; }" : "=r"(r) : "l"(p));
    return r;
}
// pack {lo, hi} floats to fp16x2 (round-to-nearest); lo in low 16 bits
__device__ __forceinline__ uint32_t f16x2(float lo, float hi) {
    uint32_t r;
    asm("cvt.rn.f16x2.f32 %0, %1, %2;" : "=r"(r) : "f"(hi), "f"(lo));
    return r;
}
__device__ __forceinline__ void ldm_x4(uint32_t* r, uint32_t addr) {
    asm volatile("ldmatrix.sync.aligned.m8n8.x4.shared.b16 {%0,%1,%2,%3}, [%4];"
        : "=r"(r[0]), "=r"(r[1]), "=r"(r[2]), "=r"(r[3]) : "r"(addr));
}
__device__ __forceinline__ void ldm_x4t(uint32_t* r, uint32_t addr) {
    asm volatile("ldmatrix.sync.aligned.m8n8.x4.trans.shared.b16 {%0,%1,%2,%3}, [%4];"
        : "=r"(r[0]), "=r"(r[1]), "=r"(r[2]), "=r"(r[3]) : "r"(addr));
}
__device__ __forceinline__ void mma_f16(float* d, const uint32_t* a, const uint32_t* b) {
    asm volatile("mma.sync.aligned.m16n8k16.row.col.f32.f16.f16.f32 "
        "{%0,%1,%2,%3}, {%4,%5,%6,%7}, {%8,%9}, {%0,%1,%2,%3};"
        : "+f"(d[0]), "+f"(d[1]), "+f"(d[2]), "+f"(d[3])
        : "r"(a[0]), "r"(a[1]), "r"(a[2]), "r"(a[3]), "r"(b[0]), "r"(b[1]));
}

// ---------------- kernel 1: NCHW -> NHWC transpose of x ----------------
__global__ void k_transpose_x(const float* __restrict__ x) {
    __shared__ float tile[32][33];
    int b  = blockIdx.z;
    int c0 = blockIdx.y * 32;
    int p0 = blockIdx.x * 32;
    int tx = threadIdx.x, ty = threadIdx.y;   // 32 x 8
    #pragma unroll
    for (int j = 0; j < 32; j += 8)
        tile[ty + j][tx] = x[((b*CI + c0 + ty + j)*HWSZ) + p0 + tx];
    __syncthreads();
    #pragma unroll
    for (int j = 0; j < 32; j += 8)
        g_xt[(b*HWSZ + p0 + ty + j)*CI + c0 + tx] = tile[tx][ty + j];
}

// ---------------- kernel 2: dcn_w -> fp16 hi/lo chunk images [chunk][k32][n256] ------
__global__ void k_prep_b(const float* __restrict__ dw) {
    int idx = blockIdx.x * 256 + threadIdx.x;
    if (idx >= NCH*8192) return;
    int kc = idx >> 13;
    int r  = idx & 8191;
    int k  = r >> 8;
    int n  = r & 255;
    int tap = kc >> 3;
    int c   = (kc & 7)*32 + k;
    float v = dw[(n*CI + c)*KKT + tap];
    __half hv = __float2half_rn(v);
    float hf = __half2float(hv);
    __half lv = __float2half_rn(v - hf);
    g_Bh16[idx] = __half_as_ushort(hv);
    g_Bl16[idx] = __half_as_ushort(lv);
}

// ---------------- kernel 2b: offset_w -> fp16 hi/lo chunk images [chunk][k32][n32] ---
__global__ void k_prep_ob(const float* __restrict__ ow) {
    int idx = blockIdx.x * 256 + threadIdx.x;
    if (idx >= NCH*1024) return;
    int kc = idx >> 10;
    int r  = idx & 1023;
    int k  = r >> 5;
    int n  = r & 31;
    int tap = kc >> 3;
    int c   = (kc & 7)*32 + k;
    float v = (n < 27) ? ow[(n*CI + c)*KKT + tap] : 0.0f;
    __half hv = __float2half_rn(v);
    float hf = __half2float(hv);
    __half lv = __float2half_rn(v - hf);
    g_oBh16[idx] = __half_as_ushort(hv);
    g_oBl16[idx] = __half_as_ushort(lv);
}

// ---------------- fused kernel: M=128 pixels per block, grid 128 (round-9 structure) -
// fp16 A single-plane; B fp16 hi/lo; 2 MMAs per fragment pair.
// SMEM byte offsets:
#define FA(f)      ((f) * 5120)                         // main A fp16, 64 x 80B
#define FB(s, f)   (10240 + ((s)*2 + (f)) * 16896)      // main B planes 32 x 528B
#define CA(f)      (10240 + (f) * 10240)                // conv A fp16 128 x 80B (overlays FB)
#define FBC(s, f)  (77824 + ((s)*2 + (f)) * 2560)       // conv B planes 32 x 80B
#define FPW        88064                                // float4[9][128]
#define FPO        106496                               // int4[9][128]
#define FSO        124928                               // float[128][33]
#define FSM_TOTAL  141824

__global__ __launch_bounds__(512, 1) void k_fused(float* __restrict__ out,
                                                  const float* __restrict__ ob) {
    extern __shared__ char sm[];
    uint32_t su = smem_u32(sm);

    int tid  = threadIdx.x;
    int lane = tid & 31;
    int wid  = tid >> 5;
    int b    = blockIdx.x >> 5;
    int hp   = blockIdx.x & 31;          // row pair: rows 2hp, 2hp+1
    int hw0  = hp * 128;
    const float* xb = g_xt + (size_t)b * HWSZ * CI;

    // common ldmatrix lane mapping
    int g  = lane >> 3, lr = lane & 7;
    int a_row = (g & 1)*8 + lr;
    int a_cb  = (g >> 1) * 16;
    int b_krow = (g & 1)*8 + lr;
    int b_cb  = (g >> 1) * 16;

    float4* spw = (float4*)(sm + FPW);
    int4*   spo = (int4*)  (sm + FPO);
    float (*so)[33] = (float(*)[33])(sm + FSO);

    // ======================= PHASE 1: offset conv (M=128, N=32) ====================
    {
        // warp tiles: 8 m16 tiles x 2 n16 pairs, all 16 warps
        int mt = wid & 7;
        int npair = wid >> 3;

        // A-build: 128 pix x 32 ch / 512 thr -> pixel tid>>2, 8 ch each
        int cgp = tid >> 2;
        int cgk = (tid & 3) * 8;
        int prow = cgp >> 6;          // 0/1 within row pair
        int pcol = cgp & 63;

        // conv B-load mapping: tid<128
        int cbr = (tid & 127) >> 2;
        int cbs = (tid & 3) * 16;
        bool bld = (tid < 128);

        float accc[2][4];
        #pragma unroll
        for (int j = 0; j < 2; ++j)
            #pragma unroll
            for (int q = 0; q < 4; ++q) accc[j][q] = 0.0f;

        // per-thread tap state
        bool valid;
        const float* asrc;
        {
            int y = 2*hp + prow - 1, xx = pcol - 1;   // tap 0
            valid = (y >= 0) && (y < HH) && (xx >= 0) && (xx < WWD);
            asrc = g_xt + (((size_t)(b*HWSZ) + (size_t)(y*WWD + xx)) * CI) + cgk;
        }

        // prologue chunk 0
        {
            if (bld) {
                cp16u(su + FBC(0,0) + cbr*80 + cbs, (const char*)g_oBh16 + (size_t)cbr*64 + cbs);
                cp16u(su + FBC(1,0) + cbr*80 + cbs, (const char*)g_oBl16 + (size_t)cbr*64 + cbs);
            }
            cp_commit();
            float4 v0 = make_float4(0,0,0,0), v1 = v0;
            if (valid) {
                v0 = *(const float4*)asrc;
                v1 = *(const float4*)(asrc + 4);
            }
            uint4 pk;
            pk.x = f16x2(v0.x, v0.y); pk.y = f16x2(v0.z, v0.w);
            pk.z = f16x2(v1.x, v1.y); pk.w = f16x2(v1.z, v1.w);
            *(uint4*)(sm + CA(0) + cgp*80 + cgk*2) = pk;
            cp_wait0();
        }
        __syncthreads();

        #pragma unroll 1
        for (int i = 0; i < NCH; ++i) {
            int buf = i & 1;

            float4 v[2];
            v[0] = make_float4(0,0,0,0); v[1] = v[0];
            if (i < NCH - 1) {
                int sn = i + 1;
                if ((sn & 7) == 0) {
                    int t = sn >> 3;
                    int y = 2*hp + prow + t/3 - 1, xx = pcol + t%3 - 1;
                    valid = (y >= 0) && (y < HH) && (xx >= 0) && (xx < WWD);
                    asrc = g_xt + (((size_t)(b*HWSZ) + (size_t)(y*WWD + xx)) * CI) + cgk;
                }
                if (valid) {
                    const float* p = asrc + (sn & 7)*32;
                    v[0] = *(const float4*)p;
                    v[1] = *(const float4*)(p + 4);
                }
                if (bld) {
                    const char* sbh = (const char*)g_oBh16 + ((size_t)sn*1024 + cbr*32)*2 + cbs;
                    const char* sbl = (const char*)g_oBl16 + ((size_t)sn*1024 + cbr*32)*2 + cbs;
                    cp16u(su + FBC(0, buf^1) + cbr*80 + cbs, sbh);
                    cp16u(su + FBC(1, buf^1) + cbr*80 + cbs, sbl);
                }
                cp_commit();
            }

            // conv MMA (2 k16 steps, 1 m16 x 2 n8, A 1-plane x B 2-plane = 2 MMAs/nt... 4 total/ks)
            {
                uint32_t baseA  = su + CA(buf) + (mt*16 + a_row)*80 + a_cb;
                uint32_t baseBh = su + FBC(0, buf) + b_krow*80 + npair*32 + b_cb;
                uint32_t baseBl = su + FBC(1, buf) + b_krow*80 + npair*32 + b_cb;
                #pragma unroll
                for (int ks = 0; ks < 2; ++ks) {
                    uint32_t aH[4];
                    ldm_x4(aH, baseA + ks*32);
                    uint32_t bH[2][2], bL[2][2], t4[4];
                    ldm_x4t(t4, baseBh + ks*1280);
                    bH[0][0]=t4[0]; bH[0][1]=t4[1]; bH[1][0]=t4[2]; bH[1][1]=t4[3];
                    ldm_x4t(t4, baseBl + ks*1280);
                    bL[0][0]=t4[0]; bL[0][1]=t4[1]; bL[1][0]=t4[2]; bL[1][1]=t4[3];
                    #pragma unroll
                    for (int nt = 0; nt < 2; ++nt) {
                        mma_f16(accc[nt], aH, bH[nt]);
                        mma_f16(accc[nt], aH, bL[nt]);
                    }
                }
            }

            if (i < NCH - 1) {
                int nb = buf ^ 1;
                uint4 pk;
                pk.x = f16x2(v[0].x, v[0].y); pk.y = f16x2(v[0].z, v[0].w);
                pk.z = f16x2(v[1].x, v[1].y); pk.w = f16x2(v[1].z, v[1].w);
                *(uint4*)(sm + CA(nb) + cgp*80 + cgk*2) = pk;
                cp_wait0();
            }
            __syncthreads();
        }

        // scatter conv result
        {
            int r0 = mt*16 + (lane >> 2);
            int c0 = npair*16 + (lane & 3)*2;
            #pragma unroll
            for (int nt = 0; nt < 2; ++nt) {
                int c = c0 + nt*8;
                so[r0][c]       = accc[nt][0];
                so[r0][c+1]     = accc[nt][1];
                so[r0 + 8][c]   = accc[nt][2];
                so[r0 + 8][c+1] = accc[nt][3];
            }
        }
        __syncthreads();
    }

    // ======================= PHASE 2: param build (128 pixels) =====================
    if (tid < 128) {
        float ov[27];
        #pragma unroll
        for (int oc = 0; oc < 27; ++oc) ov[oc] = so[tid][oc] + ob[oc];

        int w    = tid & 63;
        int hloc = 2*hp + (tid >> 6);
        #pragma unroll
        for (int kk = 0; kk < 9; ++kk) {
            float dy = ov[2*kk];
            float dx = ov[2*kk + 1];
            float m  = 1.0f / (1.0f + expf(-ov[18 + kk]));
            int ki = kk / 3, kj = kk % 3;
            float py = (float)(hloc - 1 + ki) + dy;
            float px = (float)(w - 1 + kj) + dx;
            float fy = floorf(py), fx = floorf(px);
            float wy = py - fy,    wx = px - fx;
            int y0 = (int)fy, x0 = (int)fx;
            int y1 = y0 + 1,  x1 = x0 + 1;

            bool vy0 = (y0 >= 0) && (y0 < HH);
            bool vy1 = (y1 >= 0) && (y1 < HH);
            bool vx0 = (x0 >= 0) && (x0 < WWD);
            bool vx1 = (x1 >= 0) && (x1 < WWD);

            float w00 = (1.0f - wy) * (1.0f - wx) * m * ((vy0 && vx0) ? 1.0f : 0.0f);
            float w01 = (1.0f - wy) * wx          * m * ((vy0 && vx1) ? 1.0f : 0.0f);
            float w10 = wy * (1.0f - wx)          * m * ((vy1 && vx0) ? 1.0f : 0.0f);
            float w11 = wy * wx                   * m * ((vy1 && vx1) ? 1.0f : 0.0f);

            int yc0 = min(max(y0, 0), HH - 1);
            int yc1 = min(max(y1, 0), HH - 1);
            int xc0 = min(max(x0, 0), WWD - 1);
            int xc1 = min(max(x1, 0), WWD - 1);

            spw[kk*128 + tid] = make_float4(w00, w01, w10, w11);
            spo[kk*128 + tid] = make_int4((yc0*WWD + xc0)*CI, (yc0*WWD + xc1)*CI,
                                          (yc1*WWD + xc0)*CI, (yc1*WWD + xc1)*CI);
        }
    }
    __syncthreads();

    // ======================= PHASE 3: main GEMM, two 64-pixel passes ===============
    int mh = (wid & 1) * 32;
    int ns = (wid >> 1) * 32;
    int gp = tid >> 3;
    int gk = (tid & 7) * 4;
    int br  = tid >> 4;
    int bsg = (tid & 15) * 32;

    #pragma unroll 1
    for (int pass = 0; pass < 2; ++pass) {
        int pb = pass * 64;           // pixel base within the 128-pixel block

        float acc[2][4][4];
        #pragma unroll
        for (int i = 0; i < 2; ++i)
            #pragma unroll
            for (int j = 0; j < 4; ++j)
                #pragma unroll
                for (int q = 0; q < 4; ++q) acc[i][j][q] = 0.0f;

        // prologue chunk 0
        {
            float4 wv = spw[pb + gp];
            int4   po = spo[pb + gp];
            const float* base = xb + gk;
            float4 v0 = *(const float4*)(base + po.x);
            float4 v1 = *(const float4*)(base + po.y);
            float4 v2 = *(const float4*)(base + po.z);
            float4 v3 = *(const float4*)(base + po.w);
            const char* srcb = (const char*)g_Bh16 + (size_t)br*512 + bsg;
            const char* srcl = (const char*)g_Bl16 + (size_t)br*512 + bsg;
            uint32_t dstb = su + FB(0,0) + br*528 + bsg;
            uint32_t dstl = su + FB(1,0) + br*528 + bsg;
            cp16u(dstb, srcb); cp16u(dstb + 16, srcb + 16);
            cp16u(dstl, srcl); cp16u(dstl + 16, srcl + 16);
            cp_commit();
            float4 s;
            s.x = wv.x*v0.x + wv.y*v1.x + wv.z*v2.x + wv.w*v3.x;
            s.y = wv.x*v0.y + wv.y*v1.y + wv.z*v2.y + wv.w*v3.y;
            s.z = wv.x*v0.z + wv.y*v1.z + wv.z*v2.z + wv.w*v3.z;
            s.w = wv.x*v0.w + wv.y*v1.w + wv.z*v2.w + wv.w*v3.w;
            *(uint2*)(sm + FA(0) + gp*80 + gk*2) =
                make_uint2(f16x2(s.x, s.y), f16x2(s.z, s.w));
            cp_wait0();
        }
        __syncthreads();

        #pragma unroll 1
        for (int i = 0; i < NCH; ++i) {
            int buf = i & 1;

            float4 v0, v1, v2, v3;
            float4 wv;
            if (i < NCH - 1) {
                int sn = i + 1;
                int t = sn >> 3;
                int4 po = spo[t*128 + pb + gp];
                wv = spw[t*128 + pb + gp];
                const float* base = xb + (sn & 7)*32 + gk;
                v0 = *(const float4*)(base + po.x);
                v1 = *(const float4*)(base + po.y);
                v2 = *(const float4*)(base + po.z);
                v3 = *(const float4*)(base + po.w);
                const char* srcb = (const char*)g_Bh16 + ((size_t)sn*8192 + br*256)*2 + bsg;
                const char* srcl = (const char*)g_Bl16 + ((size_t)sn*8192 + br*256)*2 + bsg;
                uint32_t dstb = su + FB(0, buf^1) + br*528 + bsg;
                uint32_t dstl = su + FB(1, buf^1) + br*528 + bsg;
                cp16u(dstb, srcb); cp16u(dstb + 16, srcb + 16);
                cp16u(dstl, srcl); cp16u(dstl + 16, srcl + 16);
                cp_commit();
            }

            uint32_t baseA  = su + FA(buf) + (mh + a_row)*80 + a_cb;
            uint32_t baseBh = su + FB(0, buf) + b_krow*528 + ns*2 + b_cb;
            uint32_t baseBl = su + FB(1, buf) + b_krow*528 + ns*2 + b_cb;
            #pragma unroll
            for (int ks = 0; ks < 2; ++ks) {
                uint32_t aH[2][4];
                ldm_x4(aH[0], baseA + ks*32);
                ldm_x4(aH[1], baseA + 1280 + ks*32);
                uint32_t bH[4][2], bL[4][2], t4[4];
                ldm_x4t(t4, baseBh + ks*8448);
                bH[0][0]=t4[0]; bH[0][1]=t4[1]; bH[1][0]=t4[2]; bH[1][1]=t4[3];
                ldm_x4t(t4, baseBh + ks*8448 + 32);
                bH[2][0]=t4[0]; bH[2][1]=t4[1]; bH[3][0]=t4[2]; bH[3][1]=t4[3];
                ldm_x4t(t4, baseBl + ks*8448);
                bL[0][0]=t4[0]; bL[0][1]=t4[1]; bL[1][0]=t4[2]; bL[1][1]=t4[3];
                ldm_x4t(t4, baseBl + ks*8448 + 32);
                bL[2][0]=t4[0]; bL[2][1]=t4[1]; bL[3][0]=t4[2]; bL[3][1]=t4[3];
                #pragma unroll
                for (int mt = 0; mt < 2; ++mt)
                    #pragma unroll
                    for (int nt = 0; nt < 4; ++nt) {
                        mma_f16(acc[mt][nt], aH[mt], bH[nt]);
                        mma_f16(acc[mt][nt], aH[mt], bL[nt]);
                    }
            }

            if (i < NCH - 1) {
                float4 s;
                s.x = wv.x*v0.x + wv.y*v1.x + wv.z*v2.x + wv.w*v3.x;
                s.y = wv.x*v0.y + wv.y*v1.y + wv.z*v2.y + wv.w*v3.y;
                s.z = wv.x*v0.z + wv.y*v1.z + wv.z*v2.z + wv.w*v3.z;
                s.w = wv.x*v0.w + wv.y*v1.w + wv.z*v2.w + wv.w*v3.w;
                *(uint2*)(sm + FA(buf^1) + gp*80 + gk*2) =
                    make_uint2(f16x2(s.x, s.y), f16x2(s.z, s.w));
                cp_wait0();
            }
            __syncthreads();
        }

        // epilogue
        {
            float* op = out + ((size_t)(b*CO))*HWSZ + hw0 + pb;
            int r0 = mh + (lane >> 2);
            int c0 = ns + (lane & 3)*2;
            #pragma unroll
            for (int mt = 0; mt < 2; ++mt) {
                int r = r0 + mt*16;
                #pragma unroll
                for (int nt = 0; nt < 4; ++nt) {
                    int c = c0 + nt*8;
                    op[(size_t)c*HWSZ + r]           = acc[mt][nt][0];
                    op[(size_t)(c+1)*HWSZ + r]       = acc[mt][nt][1];
                    op[(size_t)c*HWSZ + r + 8]       = acc[mt][nt][2];
                    op[(size_t)(c+1)*HWSZ + r + 8]   = acc[mt][nt][3];
                }
            }
        }
        __syncthreads();
    }
}

// ---------------- launch ----------------
extern "C" void kernel_launch(void* const* d_in, const int* in_sizes, int n_in,
                              void* d_out, int out_size) {
    (void)in_sizes; (void)n_in; (void)out_size;
    const float* x  = (const float*)d_in[0];   // (4,256,64,64)
    const float* ow = (const float*)d_in[1];   // (27,256,3,3)
    const float* ob = (const float*)d_in[2];   // (27,)
    const float* dw = (const float*)d_in[3];   // (256,256,3,3)
    float* out = (float*)d_out;                // (4,256,64,64)

    cudaFuncSetAttribute(k_fused, cudaFuncAttributeMaxDynamicSharedMemorySize, FSM_TOTAL);

    dim3 tb(32, 8);
    dim3 tg(HWSZ/32, CI/32, BB);
    k_transpose_x<<<tg, tb>>>(x);
    k_prep_b<<<(NCH*8192 + 255)/256, 256>>>(dw);
    k_prep_ob<<<(NCH*1024 + 255)/256, 256>>>(ow);
    k_fused<<<128, 512, FSM_TOTAL>>>(out, ob);
}

// round 16
// speedup vs baseline: 2.5540x; 1.3524x over previous
#include <cuda_runtime.h>
#include <cuda_fp16.h>
#include <math.h>
#include <stdint.h>

// Problem constants
#define BB   4
#define CI   256
#define CO   256
#define HH   64
#define WWD  64
#define HWSZ (HH*WWD)
#define KKT  9
#define NCH  72            // K = 2304 in chunks of 32 channels

// ---------------- scratch (device globals; no allocation) ----------------
__device__ float  g_xt[BB*HWSZ*CI];            // x in NHWC   (16.8 MB)
__device__ unsigned short g_B16[NCH*32*256];   // fp16 dcn_w, [chunk][k32][n256]
__device__ unsigned short g_oB16[NCH*32*32];   // fp16 offset_w, [chunk][k32][n32]

// ---------------- helpers ----------------
__device__ __forceinline__ void cp16u(uint32_t dst, const void* src) {
    asm volatile("cp.async.cg.shared.global [%0], [%1], 16;\n" :: "r"(dst), "l"(src));
}
__device__ __forceinline__ void cp_commit() {
    asm volatile("cp.async.commit_group;\n" ::);
}
__device__ __forceinline__ void cp_wait0() {
    asm volatile("cp.async.wait_group 0;\n" ::: "memory");
}
__device__ __forceinline__ uint32_t smem_u32(const void* p) {
    uint32_t r;
    asm("{ .reg .u64 t; cvta.to.shared.u64 t, %1; cvt.u32.u64 %0, t; }" : "=r"(r) : "l"(p));
    return r;
}
// pack {lo, hi} floats to fp16x2 (round-to-nearest); lo in low 16 bits
__device__ __forceinline__ uint32_t f16x2(float lo, float hi) {
    uint32_t r;
    asm("cvt.rn.f16x2.f32 %0, %1, %2;" : "=r"(r) : "f"(hi), "f"(lo));
    return r;
}
__device__ __forceinline__ void ldm_x4(uint32_t* r, uint32_t addr) {
    asm volatile("ldmatrix.sync.aligned.m8n8.x4.shared.b16 {%0,%1,%2,%3}, [%4];"
        : "=r"(r[0]), "=r"(r[1]), "=r"(r[2]), "=r"(r[3]) : "r"(addr));
}
__device__ __forceinline__ void ldm_x4t(uint32_t* r, uint32_t addr) {
    asm volatile("ldmatrix.sync.aligned.m8n8.x4.trans.shared.b16 {%0,%1,%2,%3}, [%4];"
        : "=r"(r[0]), "=r"(r[1]), "=r"(r[2]), "=r"(r[3]) : "r"(addr));
}
__device__ __forceinline__ void mma_f16(float* d, const uint32_t* a, const uint32_t* b) {
    asm volatile("mma.sync.aligned.m16n8k16.row.col.f32.f16.f16.f32 "
        "{%0,%1,%2,%3}, {%4,%5,%6,%7}, {%8,%9}, {%0,%1,%2,%3};"
        : "+f"(d[0]), "+f"(d[1]), "+f"(d[2]), "+f"(d[3])
        : "r"(a[0]), "r"(a[1]), "r"(a[2]), "r"(a[3]), "r"(b[0]), "r"(b[1]));
}

// ---------------- kernel 1: NCHW -> NHWC transpose of x ----------------
__global__ void k_transpose_x(const float* __restrict__ x) {
    __shared__ float tile[32][33];
    int b  = blockIdx.z;
    int c0 = blockIdx.y * 32;
    int p0 = blockIdx.x * 32;
    int tx = threadIdx.x, ty = threadIdx.y;   // 32 x 8
    #pragma unroll
    for (int j = 0; j < 32; j += 8)
        tile[ty + j][tx] = x[((b*CI + c0 + ty + j)*HWSZ) + p0 + tx];
    __syncthreads();
    #pragma unroll
    for (int j = 0; j < 32; j += 8)
        g_xt[(b*HWSZ + p0 + ty + j)*CI + c0 + tx] = tile[tx][ty + j];
}

// ---------------- kernel 2: dcn_w -> fp16 chunk images [chunk][k32][n256] ------------
__global__ void k_prep_b(const float* __restrict__ dw) {
    int idx = blockIdx.x * 256 + threadIdx.x;
    if (idx >= NCH*8192) return;
    int kc = idx >> 13;
    int r  = idx & 8191;
    int k  = r >> 8;
    int n  = r & 255;
    int tap = kc >> 3;
    int c   = (kc & 7)*32 + k;
    float v = dw[(n*CI + c)*KKT + tap];
    g_B16[idx] = __half_as_ushort(__float2half_rn(v));
}

// ---------------- kernel 2b: offset_w -> fp16 chunk images [chunk][k32][n32] ---------
__global__ void k_prep_ob(const float* __restrict__ ow) {
    int idx = blockIdx.x * 256 + threadIdx.x;
    if (idx >= NCH*1024) return;
    int kc = idx >> 10;
    int r  = idx & 1023;
    int k  = r >> 5;
    int n  = r & 31;
    int tap = kc >> 3;
    int c   = (kc & 7)*32 + k;
    float v = (n < 27) ? ow[(n*CI + c)*KKT + tap] : 0.0f;
    g_oB16[idx] = __half_as_ushort(__float2half_rn(v));
}

// ---------------- fused kernel: M=128 pixels per block, grid 128 ---------------------
// fp16 single-plane A AND B. Round-15 structure unchanged.
// SMEM byte offsets:
#define FA(f)      ((f) * 5120)                // main A fp16, 64 x 80B
#define FB(f)      (10240 + (f) * 16896)       // main B fp16, 32 x 528B
#define CA(f)      (10240 + (f) * 10240)       // conv A fp16 128 x 80B (overlays FB)
#define FBC(f)     (44032 + (f) * 2560)        // conv B fp16, 32 x 80B
#define FPW        49152                       // float4[9][128]
#define FPO        67584                       // int4[9][128]
#define FSO        86016                       // float[128][33]
#define FSM_TOTAL  102912

__global__ __launch_bounds__(512, 1) void k_fused(float* __restrict__ out,
                                                  const float* __restrict__ ob) {
    extern __shared__ char sm[];
    uint32_t su = smem_u32(sm);

    int tid  = threadIdx.x;
    int lane = tid & 31;
    int wid  = tid >> 5;
    int b    = blockIdx.x >> 5;
    int hp   = blockIdx.x & 31;          // row pair: rows 2hp, 2hp+1
    int hw0  = hp * 128;
    const float* xb = g_xt + (size_t)b * HWSZ * CI;

    // common ldmatrix lane mapping
    int g  = lane >> 3, lr = lane & 7;
    int a_row = (g & 1)*8 + lr;
    int a_cb  = (g >> 1) * 16;
    int b_krow = (g & 1)*8 + lr;
    int b_cb  = (g >> 1) * 16;

    float4* spw = (float4*)(sm + FPW);
    int4*   spo = (int4*)  (sm + FPO);
    float (*so)[33] = (float(*)[33])(sm + FSO);

    // ======================= PHASE 1: offset conv (M=128, N=32) ====================
    {
        // warp tiles: 8 m16 tiles x 2 n16 pairs, all 16 warps
        int mt = wid & 7;
        int npair = wid >> 3;

        // A-build: 128 pix x 32 ch / 512 thr -> pixel tid>>2, 8 ch each
        int cgp = tid >> 2;
        int cgk = (tid & 3) * 8;
        int prow = cgp >> 6;          // 0/1 within row pair
        int pcol = cgp & 63;

        // conv B-load mapping: tid<128
        int cbr = (tid & 127) >> 2;
        int cbs = (tid & 3) * 16;
        bool bld = (tid < 128);

        float accc[2][4];
        #pragma unroll
        for (int j = 0; j < 2; ++j)
            #pragma unroll
            for (int q = 0; q < 4; ++q) accc[j][q] = 0.0f;

        // per-thread tap state
        bool valid;
        const float* asrc;
        {
            int y = 2*hp + prow - 1, xx = pcol - 1;   // tap 0
            valid = (y >= 0) && (y < HH) && (xx >= 0) && (xx < WWD);
            asrc = g_xt + (((size_t)(b*HWSZ) + (size_t)(y*WWD + xx)) * CI) + cgk;
        }

        // prologue chunk 0
        {
            if (bld)
                cp16u(su + FBC(0) + cbr*80 + cbs, (const char*)g_oB16 + (size_t)cbr*64 + cbs);
            cp_commit();
            float4 v0 = make_float4(0,0,0,0), v1 = v0;
            if (valid) {
                v0 = *(const float4*)asrc;
                v1 = *(const float4*)(asrc + 4);
            }
            uint4 pk;
            pk.x = f16x2(v0.x, v0.y); pk.y = f16x2(v0.z, v0.w);
            pk.z = f16x2(v1.x, v1.y); pk.w = f16x2(v1.z, v1.w);
            *(uint4*)(sm + CA(0) + cgp*80 + cgk*2) = pk;
            cp_wait0();
        }
        __syncthreads();

        #pragma unroll 1
        for (int i = 0; i < NCH; ++i) {
            int buf = i & 1;

            float4 v[2];
            v[0] = make_float4(0,0,0,0); v[1] = v[0];
            if (i < NCH - 1) {
                int sn = i + 1;
                if ((sn & 7) == 0) {
                    int t = sn >> 3;
                    int y = 2*hp + prow + t/3 - 1, xx = pcol + t%3 - 1;
                    valid = (y >= 0) && (y < HH) && (xx >= 0) && (xx < WWD);
                    asrc = g_xt + (((size_t)(b*HWSZ) + (size_t)(y*WWD + xx)) * CI) + cgk;
                }
                if (valid) {
                    const float* p = asrc + (sn & 7)*32;
                    v[0] = *(const float4*)p;
                    v[1] = *(const float4*)(p + 4);
                }
                if (bld) {
                    const char* sbh = (const char*)g_oB16 + ((size_t)sn*1024 + cbr*32)*2 + cbs;
                    cp16u(su + FBC(buf^1) + cbr*80 + cbs, sbh);
                }
                cp_commit();
            }

            // conv MMA (2 k16 steps, 1 m16 x 2 n8, single plane)
            {
                uint32_t baseA = su + CA(buf) + (mt*16 + a_row)*80 + a_cb;
                uint32_t baseB = su + FBC(buf) + b_krow*80 + npair*32 + b_cb;
                #pragma unroll
                for (int ks = 0; ks < 2; ++ks) {
                    uint32_t aH[4];
                    ldm_x4(aH, baseA + ks*32);
                    uint32_t bH[2][2], t4[4];
                    ldm_x4t(t4, baseB + ks*1280);
                    bH[0][0]=t4[0]; bH[0][1]=t4[1]; bH[1][0]=t4[2]; bH[1][1]=t4[3];
                    #pragma unroll
                    for (int nt = 0; nt < 2; ++nt)
                        mma_f16(accc[nt], aH, bH[nt]);
                }
            }

            if (i < NCH - 1) {
                int nb = buf ^ 1;
                uint4 pk;
                pk.x = f16x2(v[0].x, v[0].y); pk.y = f16x2(v[0].z, v[0].w);
                pk.z = f16x2(v[1].x, v[1].y); pk.w = f16x2(v[1].z, v[1].w);
                *(uint4*)(sm + CA(nb) + cgp*80 + cgk*2) = pk;
                cp_wait0();
            }
            __syncthreads();
        }

        // scatter conv result
        {
            int r0 = mt*16 + (lane >> 2);
            int c0 = npair*16 + (lane & 3)*2;
            #pragma unroll
            for (int nt = 0; nt < 2; ++nt) {
                int c = c0 + nt*8;
                so[r0][c]       = accc[nt][0];
                so[r0][c+1]     = accc[nt][1];
                so[r0 + 8][c]   = accc[nt][2];
                so[r0 + 8][c+1] = accc[nt][3];
            }
        }
        __syncthreads();
    }

    // ======================= PHASE 2: param build (128 pixels) =====================
    if (tid < 128) {
        float ov[27];
        #pragma unroll
        for (int oc = 0; oc < 27; ++oc) ov[oc] = so[tid][oc] + ob[oc];

        int w    = tid & 63;
        int hloc = 2*hp + (tid >> 6);
        #pragma unroll
        for (int kk = 0; kk < 9; ++kk) {
            float dy = ov[2*kk];
            float dx = ov[2*kk + 1];
            float m  = 1.0f / (1.0f + expf(-ov[18 + kk]));
            int ki = kk / 3, kj = kk % 3;
            float py = (float)(hloc - 1 + ki) + dy;
            float px = (float)(w - 1 + kj) + dx;
            float fy = floorf(py), fx = floorf(px);
            float wy = py - fy,    wx = px - fx;
            int y0 = (int)fy, x0 = (int)fx;
            int y1 = y0 + 1,  x1 = x0 + 1;

            bool vy0 = (y0 >= 0) && (y0 < HH);
            bool vy1 = (y1 >= 0) && (y1 < HH);
            bool vx0 = (x0 >= 0) && (x0 < WWD);
            bool vx1 = (x1 >= 0) && (x1 < WWD);

            float w00 = (1.0f - wy) * (1.0f - wx) * m * ((vy0 && vx0) ? 1.0f : 0.0f);
            float w01 = (1.0f - wy) * wx          * m * ((vy0 && vx1) ? 1.0f : 0.0f);
            float w10 = wy * (1.0f - wx)          * m * ((vy1 && vx0) ? 1.0f : 0.0f);
            float w11 = wy * wx                   * m * ((vy1 && vx1) ? 1.0f : 0.0f);

            int yc0 = min(max(y0, 0), HH - 1);
            int yc1 = min(max(y1, 0), HH - 1);
            int xc0 = min(max(x0, 0), WWD - 1);
            int xc1 = min(max(x1, 0), WWD - 1);

            spw[kk*128 + tid] = make_float4(w00, w01, w10, w11);
            spo[kk*128 + tid] = make_int4((yc0*WWD + xc0)*CI, (yc0*WWD + xc1)*CI,
                                          (yc1*WWD + xc0)*CI, (yc1*WWD + xc1)*CI);
        }
    }
    __syncthreads();

    // ======================= PHASE 3: main GEMM, two 64-pixel passes ===============
    int mh = (wid & 1) * 32;
    int ns = (wid >> 1) * 32;
    int gp = tid >> 3;
    int gk = (tid & 7) * 4;
    int br  = tid >> 4;
    int bsg = (tid & 15) * 32;

    #pragma unroll 1
    for (int pass = 0; pass < 2; ++pass) {
        int pb = pass * 64;           // pixel base within the 128-pixel block

        float acc[2][4][4];
        #pragma unroll
        for (int i = 0; i < 2; ++i)
            #pragma unroll
            for (int j = 0; j < 4; ++j)
                #pragma unroll
                for (int q = 0; q < 4; ++q) acc[i][j][q] = 0.0f;

        // prologue chunk 0
        {
            float4 wv = spw[pb + gp];
            int4   po = spo[pb + gp];
            const float* base = xb + gk;
            float4 v0 = *(const float4*)(base + po.x);
            float4 v1 = *(const float4*)(base + po.y);
            float4 v2 = *(const float4*)(base + po.z);
            float4 v3 = *(const float4*)(base + po.w);
            const char* srcb = (const char*)g_B16 + (size_t)br*512 + bsg;
            uint32_t dstb = su + FB(0) + br*528 + bsg;
            cp16u(dstb, srcb); cp16u(dstb + 16, srcb + 16);
            cp_commit();
            float4 s;
            s.x = wv.x*v0.x + wv.y*v1.x + wv.z*v2.x + wv.w*v3.x;
            s.y = wv.x*v0.y + wv.y*v1.y + wv.z*v2.y + wv.w*v3.y;
            s.z = wv.x*v0.z + wv.y*v1.z + wv.z*v2.z + wv.w*v3.z;
            s.w = wv.x*v0.w + wv.y*v1.w + wv.z*v2.w + wv.w*v3.w;
            *(uint2*)(sm + FA(0) + gp*80 + gk*2) =
                make_uint2(f16x2(s.x, s.y), f16x2(s.z, s.w));
            cp_wait0();
        }
        __syncthreads();

        #pragma unroll 1
        for (int i = 0; i < NCH; ++i) {
            int buf = i & 1;

            float4 v0, v1, v2, v3;
            float4 wv;
            if (i < NCH - 1) {
                int sn = i + 1;
                int t = sn >> 3;
                int4 po = spo[t*128 + pb + gp];
                wv = spw[t*128 + pb + gp];
                const float* base = xb + (sn & 7)*32 + gk;
                v0 = *(const float4*)(base + po.x);
                v1 = *(const float4*)(base + po.y);
                v2 = *(const float4*)(base + po.z);
                v3 = *(const float4*)(base + po.w);
                const char* srcb = (const char*)g_B16 + ((size_t)sn*8192 + br*256)*2 + bsg;
                uint32_t dstb = su + FB(buf^1) + br*528 + bsg;
                cp16u(dstb, srcb); cp16u(dstb + 16, srcb + 16);
                cp_commit();
            }

            uint32_t baseA = su + FA(buf) + (mh + a_row)*80 + a_cb;
            uint32_t baseB = su + FB(buf) + b_krow*528 + ns*2 + b_cb;
            #pragma unroll
            for (int ks = 0; ks < 2; ++ks) {
                uint32_t aH[2][4];
                ldm_x4(aH[0], baseA + ks*32);
                ldm_x4(aH[1], baseA + 1280 + ks*32);
                uint32_t bH[4][2], t4[4];
                ldm_x4t(t4, baseB + ks*8448);
                bH[0][0]=t4[0]; bH[0][1]=t4[1]; bH[1][0]=t4[2]; bH[1][1]=t4[3];
                ldm_x4t(t4, baseB + ks*8448 + 32);
                bH[2][0]=t4[0]; bH[2][1]=t4[1]; bH[3][0]=t4[2]; bH[3][1]=t4[3];
                #pragma unroll
                for (int mt = 0; mt < 2; ++mt)
                    #pragma unroll
                    for (int nt = 0; nt < 4; ++nt)
                        mma_f16(acc[mt][nt], aH[mt], bH[nt]);
            }

            if (i < NCH - 1) {
                float4 s;
                s.x = wv.x*v0.x + wv.y*v1.x + wv.z*v2.x + wv.w*v3.x;
                s.y = wv.x*v0.y + wv.y*v1.y + wv.z*v2.y + wv.w*v3.y;
                s.z = wv.x*v0.z + wv.y*v1.z + wv.z*v2.z + wv.w*v3.z;
                s.w = wv.x*v0.w + wv.y*v1.w + wv.z*v2.w + wv.w*v3.w;
                *(uint2*)(sm + FA(buf^1) + gp*80 + gk*2) =
                    make_uint2(f16x2(s.x, s.y), f16x2(s.z, s.w));
                cp_wait0();
            }
            __syncthreads();
        }

        // epilogue
        {
            float* op = out + ((size_t)(b*CO))*HWSZ + hw0 + pb;
            int r0 = mh + (lane >> 2);
            int c0 = ns + (lane & 3)*2;
            #pragma unroll
            for (int mt = 0; mt < 2; ++mt) {
                int r = r0 + mt*16;
                #pragma unroll
                for (int nt = 0; nt < 4; ++nt) {
                    int c = c0 + nt*8;
                    op[(size_t)c*HWSZ + r]           = acc[mt][nt][0];
                    op[(size_t)(c+1)*HWSZ + r]       = acc[mt][nt][1];
                    op[(size_t)c*HWSZ + r + 8]       = acc[mt][nt][2];
                    op[(size_t)(c+1)*HWSZ + r + 8]   = acc[mt][nt][3];
                }
            }
        }
        __syncthreads();
    }
}

// ---------------- launch ----------------
extern "C" void kernel_launch(void* const* d_in, const int* in_sizes, int n_in,
                              void* d_out, int out_size) {
    (void)in_sizes; (void)n_in; (void)out_size;
    const float* x  = (const float*)d_in[0];   // (4,256,64,64)
    const float* ow = (const float*)d_in[1];   // (27,256,3,3)
    const float* ob = (const float*)d_in[2];   // (27,)
    const float* dw = (const float*)d_in[3];   // (256,256,3,3)
    float* out = (float*)d_out;                // (4,256,64,64)

    cudaFuncSetAttribute(k_fused, cudaFuncAttributeMaxDynamicSharedMemorySize, FSM_TOTAL);

    dim3 tb(32, 8);
    dim3 tg(HWSZ/32, CI/32, BB);
    k_transpose_x<<<tg, tb>>>(x);
    k_prep_b<<<(NCH*8192 + 255)/256, 256>>>(dw);
    k_prep_ob<<<(NCH*1024 + 255)/256, 256>>>(ow);
    k_fused<<<128, 512, FSM_TOTAL>>>(out, ob);
}

// round 17
// speedup vs baseline: 2.7149x; 1.0630x over previous
#include <cuda_runtime.h>
#include <cuda_fp16.h>
#include <math.h>
#include <stdint.h>

// Problem constants
#define BB   4
#define CI   256
#define CO   256
#define HH   64
#define WWD  64
#define HWSZ (HH*WWD)
#define KKT  9
#define NCH  72            // K = 2304 in chunks of 32 channels

// ---------------- scratch (device globals; no allocation) ----------------
__device__ float  g_xt[BB*HWSZ*CI];            // x in NHWC   (16.8 MB)
__device__ unsigned short g_B16[NCH*32*256];   // fp16 dcn_w, [chunk][k32][n256]
__device__ unsigned short g_oB16[NCH*32*32];   // fp16 offset_w, [chunk][k32][n32]

// ---------------- helpers ----------------
__device__ __forceinline__ void cp16u(uint32_t dst, const void* src) {
    asm volatile("cp.async.cg.shared.global [%0], [%1], 16;\n" :: "r"(dst), "l"(src));
}
__device__ __forceinline__ void cp_commit() {
    asm volatile("cp.async.commit_group;\n" ::);
}
__device__ __forceinline__ void cp_wait0() {
    asm volatile("cp.async.wait_group 0;\n" ::: "memory");
}
__device__ __forceinline__ uint32_t smem_u32(const void* p) {
    uint32_t r;
    asm("{ .reg .u64 t; cvta.to.shared.u64 t, %1; cvt.u32.u64 %0, t; }" : "=r"(r) : "l"(p));
    return r;
}
// pack {lo, hi} floats to fp16x2 (round-to-nearest); lo in low 16 bits
__device__ __forceinline__ uint32_t f16x2(float lo, float hi) {
    uint32_t r;
    asm("cvt.rn.f16x2.f32 %0, %1, %2;" : "=r"(r) : "f"(hi), "f"(lo));
    return r;
}
__device__ __forceinline__ void ldm_x4(uint32_t* r, uint32_t addr) {
    asm volatile("ldmatrix.sync.aligned.m8n8.x4.shared.b16 {%0,%1,%2,%3}, [%4];"
        : "=r"(r[0]), "=r"(r[1]), "=r"(r[2]), "=r"(r[3]) : "r"(addr));
}
__device__ __forceinline__ void ldm_x4t(uint32_t* r, uint32_t addr) {
    asm volatile("ldmatrix.sync.aligned.m8n8.x4.trans.shared.b16 {%0,%1,%2,%3}, [%4];"
        : "=r"(r[0]), "=r"(r[1]), "=r"(r[2]), "=r"(r[3]) : "r"(addr));
}
__device__ __forceinline__ void mma_f16(float* d, const uint32_t* a, const uint32_t* b) {
    asm volatile("mma.sync.aligned.m16n8k16.row.col.f32.f16.f16.f32 "
        "{%0,%1,%2,%3}, {%4,%5,%6,%7}, {%8,%9}, {%0,%1,%2,%3};"
        : "+f"(d[0]), "+f"(d[1]), "+f"(d[2]), "+f"(d[3])
        : "r"(a[0]), "r"(a[1]), "r"(a[2]), "r"(a[3]), "r"(b[0]), "r"(b[1]));
}

// ---------------- kernel 1: NCHW -> NHWC transpose of x ----------------
__global__ void k_transpose_x(const float* __restrict__ x) {
    __shared__ float tile[32][33];
    int b  = blockIdx.z;
    int c0 = blockIdx.y * 32;
    int p0 = blockIdx.x * 32;
    int tx = threadIdx.x, ty = threadIdx.y;   // 32 x 8
    #pragma unroll
    for (int j = 0; j < 32; j += 8)
        tile[ty + j][tx] = x[((b*CI + c0 + ty + j)*HWSZ) + p0 + tx];
    __syncthreads();
    #pragma unroll
    for (int j = 0; j < 32; j += 8)
        g_xt[(b*HWSZ + p0 + ty + j)*CI + c0 + tx] = tile[tx][ty + j];
}

// ---------------- kernel 2: dcn_w -> fp16 chunk images [chunk][k32][n256] ------------
__global__ void k_prep_b(const float* __restrict__ dw) {
    int idx = blockIdx.x * 256 + threadIdx.x;
    if (idx >= NCH*8192) return;
    int kc = idx >> 13;
    int r  = idx & 8191;
    int k  = r >> 8;
    int n  = r & 255;
    int tap = kc >> 3;
    int c   = (kc & 7)*32 + k;
    float v = dw[(n*CI + c)*KKT + tap];
    g_B16[idx] = __half_as_ushort(__float2half_rn(v));
}

// ---------------- kernel 2b: offset_w -> fp16 chunk images [chunk][k32][n32] ---------
__global__ void k_prep_ob(const float* __restrict__ ow) {
    int idx = blockIdx.x * 256 + threadIdx.x;
    if (idx >= NCH*1024) return;
    int kc = idx >> 10;
    int r  = idx & 1023;
    int k  = r >> 5;
    int n  = r & 31;
    int tap = kc >> 3;
    int c   = (kc & 7)*32 + k;
    float v = (n < 27) ? ow[(n*CI + c)*KKT + tap] : 0.0f;
    g_oB16[idx] = __half_as_ushort(__float2half_rn(v));
}

// ---------------- fused kernel: M=128 pixels per block, grid 128, merged main loop ---
// SMEM byte offsets:
#define FA(f)      ((f) * 10240)               // main A fp16, 128 x 80B
#define FB(f)      (20480 + (f) * 16896)       // main B fp16, 32 x 528B
#define CA(f)      (20480 + (f) * 10240)       // conv A fp16 128 x 80B (overlays FB)
#define FBC(f)     (54272 + (f) * 2560)        // conv B fp16, 32 x 80B
#define FPW        59392                       // float4[9][128]
#define FPO        77824                       // int4[9][128]
#define FSO        96256                       // float[128][33]
#define FSM_TOTAL  113152

__global__ __launch_bounds__(512, 1) void k_fused(float* __restrict__ out,
                                                  const float* __restrict__ ob) {
    extern __shared__ char sm[];
    uint32_t su = smem_u32(sm);

    int tid  = threadIdx.x;
    int lane = tid & 31;
    int wid  = tid >> 5;
    int b    = blockIdx.x >> 5;
    int hp   = blockIdx.x & 31;          // row pair: rows 2hp, 2hp+1
    int hw0  = hp * 128;
    const float* xb = g_xt + (size_t)b * HWSZ * CI;

    // common ldmatrix lane mapping
    int g  = lane >> 3, lr = lane & 7;
    int a_row = (g & 1)*8 + lr;
    int a_cb  = (g >> 1) * 16;
    int b_krow = (g & 1)*8 + lr;
    int b_cb  = (g >> 1) * 16;

    float4* spw = (float4*)(sm + FPW);
    int4*   spo = (int4*)  (sm + FPO);
    float (*so)[33] = (float(*)[33])(sm + FSO);

    // ======================= PHASE 1: offset conv (M=128, N=32) ====================
    {
        int mt = wid & 7;
        int npair = wid >> 3;

        int cgp = tid >> 2;
        int cgk = (tid & 3) * 8;
        int prow = cgp >> 6;
        int pcol = cgp & 63;

        int cbr = (tid & 127) >> 2;
        int cbs = (tid & 3) * 16;
        bool bld = (tid < 128);

        float accc[2][4];
        #pragma unroll
        for (int j = 0; j < 2; ++j)
            #pragma unroll
            for (int q = 0; q < 4; ++q) accc[j][q] = 0.0f;

        bool valid;
        const float* asrc;
        {
            int y = 2*hp + prow - 1, xx = pcol - 1;   // tap 0
            valid = (y >= 0) && (y < HH) && (xx >= 0) && (xx < WWD);
            asrc = g_xt + (((size_t)(b*HWSZ) + (size_t)(y*WWD + xx)) * CI) + cgk;
        }

        {
            if (bld)
                cp16u(su + FBC(0) + cbr*80 + cbs, (const char*)g_oB16 + (size_t)cbr*64 + cbs);
            cp_commit();
            float4 v0 = make_float4(0,0,0,0), v1 = v0;
            if (valid) {
                v0 = *(const float4*)asrc;
                v1 = *(const float4*)(asrc + 4);
            }
            uint4 pk;
            pk.x = f16x2(v0.x, v0.y); pk.y = f16x2(v0.z, v0.w);
            pk.z = f16x2(v1.x, v1.y); pk.w = f16x2(v1.z, v1.w);
            *(uint4*)(sm + CA(0) + cgp*80 + cgk*2) = pk;
            cp_wait0();
        }
        __syncthreads();

        #pragma unroll 1
        for (int i = 0; i < NCH; ++i) {
            int buf = i & 1;

            float4 v[2];
            v[0] = make_float4(0,0,0,0); v[1] = v[0];
            if (i < NCH - 1) {
                int sn = i + 1;
                if ((sn & 7) == 0) {
                    int t = sn >> 3;
                    int y = 2*hp + prow + t/3 - 1, xx = pcol + t%3 - 1;
                    valid = (y >= 0) && (y < HH) && (xx >= 0) && (xx < WWD);
                    asrc = g_xt + (((size_t)(b*HWSZ) + (size_t)(y*WWD + xx)) * CI) + cgk;
                }
                if (valid) {
                    const float* p = asrc + (sn & 7)*32;
                    v[0] = *(const float4*)p;
                    v[1] = *(const float4*)(p + 4);
                }
                if (bld) {
                    const char* sbh = (const char*)g_oB16 + ((size_t)sn*1024 + cbr*32)*2 + cbs;
                    cp16u(su + FBC(buf^1) + cbr*80 + cbs, sbh);
                }
                cp_commit();
            }

            {
                uint32_t baseA = su + CA(buf) + (mt*16 + a_row)*80 + a_cb;
                uint32_t baseB = su + FBC(buf) + b_krow*80 + npair*32 + b_cb;
                #pragma unroll
                for (int ks = 0; ks < 2; ++ks) {
                    uint32_t aH[4];
                    ldm_x4(aH, baseA + ks*32);
                    uint32_t bH[2][2], t4[4];
                    ldm_x4t(t4, baseB + ks*1280);
                    bH[0][0]=t4[0]; bH[0][1]=t4[1]; bH[1][0]=t4[2]; bH[1][1]=t4[3];
                    #pragma unroll
                    for (int nt = 0; nt < 2; ++nt)
                        mma_f16(accc[nt], aH, bH[nt]);
                }
            }

            if (i < NCH - 1) {
                int nb = buf ^ 1;
                uint4 pk;
                pk.x = f16x2(v[0].x, v[0].y); pk.y = f16x2(v[0].z, v[0].w);
                pk.z = f16x2(v[1].x, v[1].y); pk.w = f16x2(v[1].z, v[1].w);
                *(uint4*)(sm + CA(nb) + cgp*80 + cgk*2) = pk;
                cp_wait0();
            }
            __syncthreads();
        }

        {
            int r0 = mt*16 + (lane >> 2);
            int c0 = npair*16 + (lane & 3)*2;
            #pragma unroll
            for (int nt = 0; nt < 2; ++nt) {
                int c = c0 + nt*8;
                so[r0][c]       = accc[nt][0];
                so[r0][c+1]     = accc[nt][1];
                so[r0 + 8][c]   = accc[nt][2];
                so[r0 + 8][c+1] = accc[nt][3];
            }
        }
        __syncthreads();
    }

    // ======================= PHASE 2: param build (128 pixels) =====================
    if (tid < 128) {
        float ov[27];
        #pragma unroll
        for (int oc = 0; oc < 27; ++oc) ov[oc] = so[tid][oc] + ob[oc];

        int w    = tid & 63;
        int hloc = 2*hp + (tid >> 6);
        #pragma unroll
        for (int kk = 0; kk < 9; ++kk) {
            float dy = ov[2*kk];
            float dx = ov[2*kk + 1];
            float m  = 1.0f / (1.0f + expf(-ov[18 + kk]));
            int ki = kk / 3, kj = kk % 3;
            float py = (float)(hloc - 1 + ki) + dy;
            float px = (float)(w - 1 + kj) + dx;
            float fy = floorf(py), fx = floorf(px);
            float wy = py - fy,    wx = px - fx;
            int y0 = (int)fy, x0 = (int)fx;
            int y1 = y0 + 1,  x1 = x0 + 1;

            bool vy0 = (y0 >= 0) && (y0 < HH);
            bool vy1 = (y1 >= 0) && (y1 < HH);
            bool vx0 = (x0 >= 0) && (x0 < WWD);
            bool vx1 = (x1 >= 0) && (x1 < WWD);

            float w00 = (1.0f - wy) * (1.0f - wx) * m * ((vy0 && vx0) ? 1.0f : 0.0f);
            float w01 = (1.0f - wy) * wx          * m * ((vy0 && vx1) ? 1.0f : 0.0f);
            float w10 = wy * (1.0f - wx)          * m * ((vy1 && vx0) ? 1.0f : 0.0f);
            float w11 = wy * wx                   * m * ((vy1 && vx1) ? 1.0f : 0.0f);

            int yc0 = min(max(y0, 0), HH - 1);
            int yc1 = min(max(y1, 0), HH - 1);
            int xc0 = min(max(x0, 0), WWD - 1);
            int xc1 = min(max(x1, 0), WWD - 1);

            spw[kk*128 + tid] = make_float4(w00, w01, w10, w11);
            spo[kk*128 + tid] = make_int4((yc0*WWD + xc0)*CI, (yc0*WWD + xc1)*CI,
                                          (yc1*WWD + xc0)*CI, (yc1*WWD + xc1)*CI);
        }
    }
    __syncthreads();

    // ======================= PHASE 3: merged main GEMM, M=128, 72 iterations =======
    {
        int mg = (wid & 3) * 32;          // warp pixel group (32 pix, 2 m16 tiles)
        int ng = (wid >> 2) * 64;         // warp n base (64 n, 8 n8 tiles)

        // A-build: 128 pix x 32 ch / 512 thr -> 8 ch/thread, two 4-ch substeps
        int gp = tid >> 2;                // pixel 0..127
        int gk = (tid & 3) * 8;           // channel base
        // B-load: 32 rows x 512B / 512 thr -> 32B per thread
        int br  = tid >> 4;               // k row 0..31
        int bsg = (tid & 15) * 32;

        float acc[2][8][4];
        #pragma unroll
        for (int i = 0; i < 2; ++i)
            #pragma unroll
            for (int j = 0; j < 8; ++j)
                #pragma unroll
                for (int q = 0; q < 4; ++q) acc[i][j][q] = 0.0f;

#define MLOADB(sn, bufw) do { \
    const char* srcb = (const char*)g_B16 + ((size_t)(sn)*8192 + br*256)*2 + bsg; \
    uint32_t dstb = su + FB(bufw) + br*528 + bsg; \
    cp16u(dstb, srcb); cp16u(dstb + 16, srcb + 16); \
    cp_commit(); \
} while (0)

#define MGATH(off) do { \
    v0 = *(const float4*)(base0 + po.x + (off)); \
    v1 = *(const float4*)(base0 + po.y + (off)); \
    v2 = *(const float4*)(base0 + po.z + (off)); \
    v3 = *(const float4*)(base0 + po.w + (off)); \
} while (0)

#define MBSTORE(bufw, off) do { \
    float4 s; \
    s.x = wv.x*v0.x + wv.y*v1.x + wv.z*v2.x + wv.w*v3.x; \
    s.y = wv.x*v0.y + wv.y*v1.y + wv.z*v2.y + wv.w*v3.y; \
    s.z = wv.x*v0.z + wv.y*v1.z + wv.z*v2.z + wv.w*v3.z; \
    s.w = wv.x*v0.w + wv.y*v1.w + wv.z*v2.w + wv.w*v3.w; \
    *(uint2*)(sm + FA(bufw) + gp*80 + (gk + (off))*2) = \
        make_uint2(f16x2(s.x, s.y), f16x2(s.z, s.w)); \
} while (0)

#define MMMA(ks) do { \
    uint32_t baseA = su + FA(buf) + (mg + a_row)*80 + a_cb; \
    uint32_t baseB = su + FB(buf) + b_krow*528 + ng*2 + b_cb; \
    uint32_t aH[2][4]; \
    ldm_x4(aH[0], baseA + (ks)*32); \
    ldm_x4(aH[1], baseA + 1280 + (ks)*32); \
    _Pragma("unroll") \
    for (int nh2 = 0; nh2 < 4; ++nh2) { \
        uint32_t bH[2][2], t4[4]; \
        ldm_x4t(t4, baseB + (ks)*8448 + nh2*32); \
        bH[0][0]=t4[0]; bH[0][1]=t4[1]; bH[1][0]=t4[2]; bH[1][1]=t4[3]; \
        _Pragma("unroll") \
        for (int mt = 0; mt < 2; ++mt) \
            _Pragma("unroll") \
            for (int nt = 0; nt < 2; ++nt) \
                mma_f16(acc[mt][nh2*2 + nt], aH[mt], bH[nt]); \
    } \
} while (0)

        // prologue chunk 0
        {
            int4   po = spo[gp];
            float4 wv = spw[gp];
            MLOADB(0, 0);
            const float* base0 = xb + gk;
            float4 v0, v1, v2, v3;
            MGATH(0);
            MBSTORE(0, 0);
            MGATH(4);
            MBSTORE(0, 4);
            cp_wait0();
        }
        __syncthreads();

        #pragma unroll 1
        for (int i = 0; i < NCH; ++i) {
            int buf = i & 1;

            int4   po;
            float4 wv;
            const float* base0 = 0;
            float4 v0, v1, v2, v3;
            if (i < NCH - 1) {
                int sn = i + 1;
                int t = sn >> 3;
                po = spo[t*128 + gp];
                wv = spw[t*128 + gp];
                base0 = xb + (sn & 7)*32 + gk;
                MLOADB(sn, buf^1);
                MGATH(0);
            }

            MMMA(0);

            if (i < NCH - 1) {
                MBSTORE(buf^1, 0);
                MGATH(4);
            }

            MMMA(1);

            if (i < NCH - 1) {
                MBSTORE(buf^1, 4);
                cp_wait0();
            }
            __syncthreads();
        }

        // epilogue: out[b][n][h][w]
        {
            float* op = out + ((size_t)(b*CO))*HWSZ + hw0;
            int r0 = mg + (lane >> 2);
            int c0 = ng + (lane & 3)*2;
            #pragma unroll
            for (int mt = 0; mt < 2; ++mt) {
                int r = r0 + mt*16;
                #pragma unroll
                for (int j = 0; j < 8; ++j) {
                    int c = c0 + j*8;
                    op[(size_t)c*HWSZ + r]           = acc[mt][j][0];
                    op[(size_t)(c+1)*HWSZ + r]       = acc[mt][j][1];
                    op[(size_t)c*HWSZ + r + 8]       = acc[mt][j][2];
                    op[(size_t)(c+1)*HWSZ + r + 8]   = acc[mt][j][3];
                }
            }
        }
    }
}

// ---------------- launch ----------------
extern "C" void kernel_launch(void* const* d_in, const int* in_sizes, int n_in,
                              void* d_out, int out_size) {
    (void)in_sizes; (void)n_in; (void)out_size;
    const float* x  = (const float*)d_in[0];   // (4,256,64,64)
    const float* ow = (const float*)d_in[1];   // (27,256,3,3)
    const float* ob = (const float*)d_in[2];   // (27,)
    const float* dw = (const float*)d_in[3];   // (256,256,3,3)
    float* out = (float*)d_out;                // (4,256,64,64)

    cudaFuncSetAttribute(k_fused, cudaFuncAttributeMaxDynamicSharedMemorySize, FSM_TOTAL);

    dim3 tb(32, 8);
    dim3 tg(HWSZ/32, CI/32, BB);
    k_transpose_x<<<tg, tb>>>(x);
    k_prep_b<<<(NCH*8192 + 255)/256, 256>>>(dw);
    k_prep_ob<<<(NCH*1024 + 255)/256, 256>>>(ow);
    k_fused<<<128, 512, FSM_TOTAL>>>(out, ob);
}